// round 8
// baseline (speedup 1.0000x reference)
#include <cuda_runtime.h>
#include <cuda_fp16.h>
#include <cstdint>

// Radon transform, ray-driven bilinear, matching the JAX reference
// (zero-filled SMEM sampling == reference's per-corner valid masking).
//
// x: (32, 1, 512, 512) f32   ->  out: (32, 1, 512, 180) f32
//
// 90-degree symmetry (R4): theta-sampled rotated image gives BOTH
//   sino[theta][u]    = row sums  (over v)
//   sino[theta+90][b] = column sums (over u) at v = 511-b
// fp16 vertical-pair tile (R6): 2 LDS per bilinear sample.
//
// R8 changes vs R7 (occ capped at 6 blocks/SM, 8% wave tail):
//  - TV=32: tile bbox <= 75x77 half2 words = 23.1KB -> 8 blocks/SM with
//    __launch_bounds__(256,8) (32 regs) = 64 warps = 100% theoretical occ.
//  - grid (90,32,4): 2x2 (u-half, v-half) block split -> 11520 blocks,
//    ~9.7 waves, tail ~3%. Row sums and column sums each get exactly TWO
//    atomicAdd contributors (commutative fp add -> bitwise deterministic).

namespace {
constexpr int Hh = 512;
constexpr int Ww = 512;
constexpr int NA = 180;
constexpr int TV = 32;            // v-tile size
constexpr int PITCH = 77;         // words per pair-row (odd), cols <= 76
constexpr int PAIR_ROWS = 75;     // pair-rows <= 75
constexpr int TILE_WORDS = PAIR_ROWS * PITCH;       // 5775 half2-words
constexpr int THREADS = 256;                        // 8 warps
constexpr int VSUM = 256;                           // v-half extent
constexpr int SMEM_BYTES = (TILE_WORDS + VSUM) * 4; // 24124 B
constexpr int UT_PER_BLOCK = 4;   // u-strips of 64 per block
constexpr int VT_PER_BLOCK = 8;   // v-tiles of 32 per block
}

// pack two f32 into f16x2: lo = f16(lo_f) (row p), hi = f16(hi_f) (row p+1)
__device__ __forceinline__ unsigned pack_h2(float hi_f, float lo_f) {
    unsigned d;
    asm("cvt.rn.f16x2.f32 %0, %1, %2;" : "=r"(d) : "f"(hi_f), "f"(lo_f));
    return d;
}

__global__ __launch_bounds__(THREADS, 8)
void radon_kernel(const float* __restrict__ x, float* __restrict__ out) {
    extern __shared__ float sm[];
    unsigned* tilew = (unsigned*)sm;        // 5775 half2 words (aliased scratch)
    float* vsum = sm + TILE_WORDS;          // 256 floats, persistent

    const int tid  = threadIdx.x;
    const int lane = tid & 31;
    const int wid  = tid >> 5;
    const int a    = blockIdx.x;   // 0..89
    const int n    = blockIdx.y;   // 0..31
    const int zu   = blockIdx.z & 1;        // u-half
    const int zv   = blockIdx.z >> 1;       // v-half
    const int v_base = zv * VSUM;

    const float theta = (float)a * 0.017453292519943295f;
    float s, c;
    sincosf(theta, &s, &c);

    const float* __restrict__ img = x + (size_t)n * (size_t)(Hh * Ww);

    // zero v-accumulator (ordered before first gather by the staging barrier)
    for (int i = tid; i < VSUM; i += THREADS) vsum[i] = 0.0f;

    const float dux =  32.0f * c;   // ix step per +32 u
    const float duy = -32.0f * s;   // iy step per +32 u
    const float dvx =   8.0f * s;   // ix step per +8 v
    const float dvy =   8.0f * c;   // iy step per +8 v

    for (int ut = 0; ut < UT_PER_BLOCK; ++ut) {
        const int u0 = (zu * UT_PER_BLOCK + ut) * 64;
        const float fu_lo = (float)u0 - 255.5f;
        const float fu_hi = fu_lo + 63.0f;
        float acc0 = 0.f, acc1 = 0.f;

        for (int vti = 0; vti < VT_PER_BLOCK; ++vti) {
            const int vt = v_base + vti * TV;
            // --- bounding box of sample footprint for this (u,v) tile ---
            const float fv_lo = (float)vt - 255.5f;
            const float fv_hi = fv_lo + (float)(TV - 1);

            const float x00 = c * fu_lo + s * fv_lo, x01 = c * fu_lo + s * fv_hi;
            const float x10 = c * fu_hi + s * fv_lo, x11 = c * fu_hi + s * fv_hi;
            const float ixmin = fminf(fminf(x00, x01), fminf(x10, x11)) + 255.5f;
            const float ixmax = fmaxf(fmaxf(x00, x01), fmaxf(x10, x11)) + 255.5f;

            const float y00 = -s * fu_lo + c * fv_lo, y01 = -s * fu_lo + c * fv_hi;
            const float y10 = -s * fu_hi + c * fv_lo, y11 = -s * fu_hi + c * fv_hi;
            const float iymin = fminf(fminf(y00, y01), fminf(y10, y11)) + 255.5f;
            const float iymax = fmaxf(fmaxf(y00, y01), fmaxf(y10, y11)) + 255.5f;

            const int c_lo = (int)floorf(ixmin) - 1;
            const int cols = ((int)floorf(ixmax) + 2) - c_lo + 1;   // <= 76
            const int r_lo = (int)floorf(iymin) - 1;
            const int rows = ((int)floorf(iymax) + 2) - r_lo + 1;   // <= 76
            const int prs  = rows - 1;                              // <= 75

            // tile entirely outside the image -> contribution is exactly 0
            if ((c_lo >= Ww) | (r_lo >= Hh) |
                (c_lo + cols <= 0) | (r_lo + rows <= 0))
                continue;

            // per-warp contiguous pair-row block (register row-carry)
            const int npr   = (prs + 7) >> 3;
            const int pr_lo = wid * npr;
            const int pr_hi = min(pr_lo + npr, prs);

            const bool interior = (c_lo >= 0) & (c_lo + cols <= Ww) &
                                  (r_lo >= 0) & (r_lo + rows <= Hh);

            if (pr_lo < pr_hi) {
                const bool ok1 = (lane + 32 < cols);
                const bool ok2 = (lane + 64 < cols);
                if (interior) {
                    const float* srcp = img + (size_t)(r_lo + pr_lo) * Ww
                                        + c_lo + lane;
                    float p0 = srcp[0];
                    float p1 = ok1 ? srcp[32] : 0.f;
                    float p2 = ok2 ? srcp[64] : 0.f;
                    for (int pr = pr_lo; pr < pr_hi; ++pr) {
                        srcp += Ww;
                        const float c0 = srcp[0];
                        const float c1 = ok1 ? srcp[32] : 0.f;
                        const float c2 = ok2 ? srcp[64] : 0.f;
                        unsigned* d = tilew + pr * PITCH + lane;
                        d[0] = pack_h2(c0, p0);
                        if (ok1) d[32] = pack_h2(c1, p1);
                        if (ok2) d[64] = pack_h2(c2, p2);
                        p0 = c0; p1 = c1; p2 = c2;
                    }
                } else {
                    const int g0 = c_lo + lane;
                    const int g1 = g0 + 32;
                    const int g2 = g0 + 64;
                    const bool c0ok = ((unsigned)g0 < (unsigned)Ww);
                    const bool c1ok = ok1 && ((unsigned)g1 < (unsigned)Ww);
                    const bool c2ok = ok2 && ((unsigned)g2 < (unsigned)Ww);
                    const int gc0 = min(max(g0, 0), Ww - 1);
                    const int gc1 = min(max(g1, 0), Ww - 1);
                    const int gc2 = min(max(g2, 0), Ww - 1);

                    int gr = r_lo + pr_lo;
                    bool rok = ((unsigned)gr < (unsigned)Hh);
                    const float* srcp =
                        img + (size_t)min(max(gr, 0), Hh - 1) * Ww;
                    float p0 = (rok & c0ok) ? srcp[gc0] : 0.f;
                    float p1 = (rok & c1ok) ? srcp[gc1] : 0.f;
                    float p2 = (rok & c2ok) ? srcp[gc2] : 0.f;
                    for (int pr = pr_lo; pr < pr_hi; ++pr) {
                        gr = r_lo + pr + 1;
                        rok = ((unsigned)gr < (unsigned)Hh);
                        srcp = img + (size_t)min(max(gr, 0), Hh - 1) * Ww;
                        const float c0 = (rok & c0ok) ? srcp[gc0] : 0.f;
                        const float c1 = (rok & c1ok) ? srcp[gc1] : 0.f;
                        const float c2 = (rok & c2ok) ? srcp[gc2] : 0.f;
                        unsigned* d = tilew + pr * PITCH + lane;
                        d[0] = pack_h2(c0, p0);
                        if (ok1) d[32] = pack_h2(c1, p1);
                        if (ok2) d[64] = pack_h2(c2, p2);
                        p0 = c0; p1 = c1; p2 = c2;
                    }
                }
            }
            __syncthreads();

            // --- gather + bilinear: warp wid handles v = vt + wid + 8k ---
            const __half2* tp = (const __half2*)tilew;
            const float fu = (float)(u0 + lane) - 255.5f;
            const float fv = (float)(vt + wid) - 255.5f;
            float bx = fmaf(c, fu, fmaf(s, fv, 255.5f)) - (float)c_lo;
            float by = fmaf(-s, fu, fmaf(c, fv, 255.5f)) - (float)r_lo;

            #pragma unroll
            for (int k = 0; k < TV / 8; ++k) {
                float s0, s1;
                {   // u = u0 + lane
                    const float fx0 = floorf(bx);
                    const float fy0 = floorf(by);
                    const float fx = bx - fx0;
                    const float fy = by - fy0;
                    const int idx = (int)fmaf(fy0, (float)PITCH, fx0);
                    const __half2 w0 = tp[idx];       // (v00, v10)
                    const __half2 w1 = tp[idx + 1];   // (v01, v11)
                    const __half2 fx2 = __float2half2_rn(fx);
                    const __half2 tb = __hfma2(fx2, __hsub2(w1, w0), w0);
                    const float top = __low2float(tb);
                    const float bot = __high2float(tb);
                    s0 = fmaf(fy, bot - top, top);
                }
                {   // u = u0 + 32 + lane
                    const float ix = bx + dux;
                    const float iy = by + duy;
                    const float fx0 = floorf(ix);
                    const float fy0 = floorf(iy);
                    const float fx = ix - fx0;
                    const float fy = iy - fy0;
                    const int idx = (int)fmaf(fy0, (float)PITCH, fx0);
                    const __half2 w0 = tp[idx];
                    const __half2 w1 = tp[idx + 1];
                    const __half2 fx2 = __float2half2_rn(fx);
                    const __half2 tb = __hfma2(fx2, __hsub2(w1, w0), w0);
                    const float top = __low2float(tb);
                    const float bot = __high2float(tb);
                    s1 = fmaf(fy, bot - top, top);
                }
                acc0 += s0;
                acc1 += s1;

                // v-sum across the 64 u's of this tile at v = vt + wid + 8k
                float pv = s0 + s1;
                #pragma unroll
                for (int m = 16; m > 0; m >>= 1)
                    pv += __shfl_xor_sync(0xffffffffu, pv, m);
                if (lane == 0) vsum[(vt - v_base) + wid + 8 * k] += pv;

                bx += dvx;
                by += dvy;
            }
            __syncthreads();   // tile reused by next stage / scratch alias
        }

        // --- u-strip reduction (scratch aliases tile region); 2 v-half
        //     contributors -> atomicAdd (commutative, deterministic) ---
        float* scratch = (float*)tilew;
        scratch[lane * 8 + wid]        = acc0;
        scratch[(32 + lane) * 8 + wid] = acc1;
        __syncthreads();
        if (tid < 64) {
            const float* p = scratch + tid * 8;
            const float tot = ((p[0] + p[1]) + (p[2] + p[3])) +
                              ((p[4] + p[5]) + (p[6] + p[7]));
            atomicAdd(&out[((size_t)(n * Ww + (u0 + tid))) * NA + a], tot);
        }
        __syncthreads();
    }

    // --- paired angle: sino[a+90][b] += vsum; 2 u-half contributors ---
    for (int i = tid; i < VSUM; i += THREADS)
        atomicAdd(&out[((size_t)(n * Ww + (511 - (v_base + i)))) * NA + (a + 90)],
                  vsum[i]);
}

extern "C" void kernel_launch(void* const* d_in, const int* in_sizes, int n_in,
                              void* d_out, int out_size) {
    (void)in_sizes; (void)n_in;
    const float* x = (const float*)d_in[0];
    float* out = (float*)d_out;

    cudaFuncSetAttribute(radon_kernel,
                         cudaFuncAttributeMaxDynamicSharedMemorySize,
                         SMEM_BYTES);

    cudaMemsetAsync(out, 0, (size_t)out_size * sizeof(float), 0);

    dim3 grid(90, 32, 4);   // (angle pair, image, u-half x v-half)
    radon_kernel<<<grid, THREADS, SMEM_BYTES>>>(x, out);
}

// round 9
// speedup vs baseline: 1.2848x; 1.2848x over previous
#include <cuda_runtime.h>
#include <cuda_fp16.h>
#include <cstdint>

// Radon transform, ray-driven bilinear, matching the JAX reference
// (zero-filled SMEM sampling == reference's per-corner valid masking).
//
// x: (32, 1, 512, 512) f32   ->  out: (32, 1, 512, 180) f32
//
// 90-degree symmetry (R4): theta-sampled rotated image gives BOTH
//   sino[theta][u]    = row sums  (over v)
//   sino[theta+90][b] = column sums (over u) at v = 511-b
// fp16 vertical-pair tile (R6): 2 LDS per bilinear sample.
//
// R9 = R7 geometry (TV=64, 6 blocks/SM, grid 90x32x2; R8's TV=32/8-block
// variant regressed: L1-wavefront bound, not occupancy bound) PLUS:
//   PER-ANGLE PITCH SELECTION. Gather lane stride in tile words is
//   delta ~ c - s*PITCH; when delta = 0 (mod 32) all 32 lanes hit distinct
//   words of ONE bank -> 32-way LDS serialization (hits theta ~ 20.3, 43.1
//   deg for fixed P=95; 16-way at ~10, 31 deg...). Once per block, pick the
//   odd pitch in [cols_bound, 8960/(rows-1)] minimizing the simulated
//   32-lane bank-0 multiplicity of the stride pattern.

namespace {
constexpr int Hh = 512;
constexpr int Ww = 512;
constexpr int NA = 180;
constexpr int TT = 64;            // tile size in u and v
constexpr int TILE_BUDGET = 8960; // tile words; +512 vsum = 37888 B (6/SM)
constexpr int THREADS = 256;      // 8 warps
constexpr int SMEM_BYTES = (TILE_BUDGET + 512) * 4;
constexpr int UT_PER_BLOCK = 4;
}

// pack two f32 into f16x2: lo = f16(lo_f) (row p), hi = f16(hi_f) (row p+1)
__device__ __forceinline__ unsigned pack_h2(float hi_f, float lo_f) {
    unsigned d;
    asm("cvt.rn.f16x2.f32 %0, %1, %2;" : "=r"(d) : "f"(hi_f), "f"(lo_f));
    return d;
}

__global__ __launch_bounds__(THREADS, 6)
void radon_kernel(const float* __restrict__ x, float* __restrict__ out) {
    extern __shared__ float sm[];
    unsigned* tilew = (unsigned*)sm;        // <=8960 half2 words (+scratch alias)
    float* vsum = sm + TILE_BUDGET;         // 512 floats, persistent

    const int tid  = threadIdx.x;
    const int lane = tid & 31;
    const int wid  = tid >> 5;
    const int a    = blockIdx.x;   // 0..89
    const int n    = blockIdx.y;   // 0..31
    const int z    = blockIdx.z;   // 0..1: u-half

    const float theta = (float)a * 0.017453292519943295f;
    float s, c;
    sincosf(theta, &s, &c);

    const float* __restrict__ img = x + (size_t)n * (size_t)(Hh * Ww);

    // zero v-accumulator (ordered before first gather by the staging barrier)
    for (int i = tid; i < 512; i += THREADS) vsum[i] = 0.0f;

    // ---- per-angle pitch selection (uniform across block, once) ----
    // bbox dims bound: cols,rows <= ceil(63*(c+s)) + 4 <= 94
    const int dim_b = (int)ceilf(63.0f * (c + s)) + 4;
    int pitch = dim_b | 1;
    {
        int bestScore = 1000;
        const int pmax_fit = TILE_BUDGET / (dim_b > 1 ? (dim_b - 1) : 1);
        const int p_first = dim_b | 1;
        for (int P = p_first; P <= pmax_fit && P <= p_first + 18; P += 2) {
            const float dm = remainderf(c - s * (float)P, 32.0f);
            int cnt = 0;
            #pragma unroll
            for (int l = 0; l < 32; ++l)
                cnt += ((((int)floorf((float)l * dm)) & 31) == 0);
            if (cnt < bestScore) { bestScore = cnt; pitch = P; }
        }
    }
    const float fpitch = (float)pitch;

    const float dux =  32.0f * c;   // ix step per +32 u
    const float duy = -32.0f * s;   // iy step per +32 u
    const float dvx =   8.0f * s;   // ix step per +8 v
    const float dvy =   8.0f * c;   // iy step per +8 v

    for (int ut = 0; ut < UT_PER_BLOCK; ++ut) {
        const int u0 = (z * UT_PER_BLOCK + ut) * TT;
        const float fu_lo = (float)u0 - 255.5f;
        const float fu_hi = fu_lo + (float)(TT - 1);
        float acc0 = 0.f, acc1 = 0.f;

        for (int vt = 0; vt < Hh; vt += TT) {
            // --- bounding box of sample footprint for this (u,v) tile ---
            const float fv_lo = (float)vt - 255.5f;
            const float fv_hi = fv_lo + (float)(TT - 1);

            const float x00 = c * fu_lo + s * fv_lo, x01 = c * fu_lo + s * fv_hi;
            const float x10 = c * fu_hi + s * fv_lo, x11 = c * fu_hi + s * fv_hi;
            const float ixmin = fminf(fminf(x00, x01), fminf(x10, x11)) + 255.5f;
            const float ixmax = fmaxf(fmaxf(x00, x01), fmaxf(x10, x11)) + 255.5f;

            const float y00 = -s * fu_lo + c * fv_lo, y01 = -s * fu_lo + c * fv_hi;
            const float y10 = -s * fu_hi + c * fv_lo, y11 = -s * fu_hi + c * fv_hi;
            const float iymin = fminf(fminf(y00, y01), fminf(y10, y11)) + 255.5f;
            const float iymax = fmaxf(fmaxf(y00, y01), fmaxf(y10, y11)) + 255.5f;

            const int c_lo = (int)floorf(ixmin) - 1;
            const int cols = ((int)floorf(ixmax) + 2) - c_lo + 1;   // <= dim_b
            const int r_lo = (int)floorf(iymin) - 1;
            const int rows = ((int)floorf(iymax) + 2) - r_lo + 1;   // <= dim_b
            const int prs  = rows - 1;

            // tile entirely outside the image -> contribution is exactly 0
            if ((c_lo >= Ww) | (r_lo >= Hh) |
                (c_lo + cols <= 0) | (r_lo + rows <= 0))
                continue;

            // per-warp contiguous pair-row block (register row-carry)
            const int npr   = (prs + 7) >> 3;
            const int pr_lo = wid * npr;
            const int pr_hi = min(pr_lo + npr, prs);

            const bool interior = (c_lo >= 0) & (c_lo + cols <= Ww) &
                                  (r_lo >= 0) & (r_lo + rows <= Hh);

            if (pr_lo < pr_hi) {
                const bool ok1 = (lane + 32 < cols);
                const bool ok2 = (lane + 64 < cols);
                if (interior) {
                    const float* srcp = img + (size_t)(r_lo + pr_lo) * Ww
                                        + c_lo + lane;
                    float p0 = srcp[0];
                    float p1 = ok1 ? srcp[32] : 0.f;
                    float p2 = ok2 ? srcp[64] : 0.f;
                    for (int pr = pr_lo; pr < pr_hi; ++pr) {
                        srcp += Ww;
                        const float c0 = srcp[0];
                        const float c1 = ok1 ? srcp[32] : 0.f;
                        const float c2 = ok2 ? srcp[64] : 0.f;
                        unsigned* d = tilew + pr * pitch + lane;
                        d[0] = pack_h2(c0, p0);
                        if (ok1) d[32] = pack_h2(c1, p1);
                        if (ok2) d[64] = pack_h2(c2, p2);
                        p0 = c0; p1 = c1; p2 = c2;
                    }
                } else {
                    const int g0 = c_lo + lane;
                    const int g1 = g0 + 32;
                    const int g2 = g0 + 64;
                    const bool c0ok = ((unsigned)g0 < (unsigned)Ww);
                    const bool c1ok = ok1 && ((unsigned)g1 < (unsigned)Ww);
                    const bool c2ok = ok2 && ((unsigned)g2 < (unsigned)Ww);
                    const int gc0 = min(max(g0, 0), Ww - 1);
                    const int gc1 = min(max(g1, 0), Ww - 1);
                    const int gc2 = min(max(g2, 0), Ww - 1);

                    int gr = r_lo + pr_lo;
                    bool rok = ((unsigned)gr < (unsigned)Hh);
                    const float* srcp =
                        img + (size_t)min(max(gr, 0), Hh - 1) * Ww;
                    float p0 = (rok & c0ok) ? srcp[gc0] : 0.f;
                    float p1 = (rok & c1ok) ? srcp[gc1] : 0.f;
                    float p2 = (rok & c2ok) ? srcp[gc2] : 0.f;
                    for (int pr = pr_lo; pr < pr_hi; ++pr) {
                        gr = r_lo + pr + 1;
                        rok = ((unsigned)gr < (unsigned)Hh);
                        srcp = img + (size_t)min(max(gr, 0), Hh - 1) * Ww;
                        const float c0 = (rok & c0ok) ? srcp[gc0] : 0.f;
                        const float c1 = (rok & c1ok) ? srcp[gc1] : 0.f;
                        const float c2 = (rok & c2ok) ? srcp[gc2] : 0.f;
                        unsigned* d = tilew + pr * pitch + lane;
                        d[0] = pack_h2(c0, p0);
                        if (ok1) d[32] = pack_h2(c1, p1);
                        if (ok2) d[64] = pack_h2(c2, p2);
                        p0 = c0; p1 = c1; p2 = c2;
                    }
                }
            }
            __syncthreads();

            // --- gather + bilinear: warp wid handles v = vt + wid + 8k ---
            const __half2* tp = (const __half2*)tilew;
            const float fu = (float)(u0 + lane) - 255.5f;
            const float fv = (float)(vt + wid) - 255.5f;
            float bx = fmaf(c, fu, fmaf(s, fv, 255.5f)) - (float)c_lo;
            float by = fmaf(-s, fu, fmaf(c, fv, 255.5f)) - (float)r_lo;

            #pragma unroll
            for (int k = 0; k < 8; ++k) {
                float s0, s1;
                {   // u = u0 + lane
                    const float fx0 = floorf(bx);
                    const float fy0 = floorf(by);
                    const float fx = bx - fx0;
                    const float fy = by - fy0;
                    const int idx = (int)fmaf(fy0, fpitch, fx0);
                    const __half2 w0 = tp[idx];       // (v00, v10)
                    const __half2 w1 = tp[idx + 1];   // (v01, v11)
                    const __half2 fx2 = __float2half2_rn(fx);
                    const __half2 tb = __hfma2(fx2, __hsub2(w1, w0), w0);
                    const float top = __low2float(tb);
                    const float bot = __high2float(tb);
                    s0 = fmaf(fy, bot - top, top);
                }
                {   // u = u0 + 32 + lane
                    const float ix = bx + dux;
                    const float iy = by + duy;
                    const float fx0 = floorf(ix);
                    const float fy0 = floorf(iy);
                    const float fx = ix - fx0;
                    const float fy = iy - fy0;
                    const int idx = (int)fmaf(fy0, fpitch, fx0);
                    const __half2 w0 = tp[idx];
                    const __half2 w1 = tp[idx + 1];
                    const __half2 fx2 = __float2half2_rn(fx);
                    const __half2 tb = __hfma2(fx2, __hsub2(w1, w0), w0);
                    const float top = __low2float(tb);
                    const float bot = __high2float(tb);
                    s1 = fmaf(fy, bot - top, top);
                }
                acc0 += s0;
                acc1 += s1;

                // v-sum across the 64 u's of this tile at v = vt + wid + 8k
                float pv = s0 + s1;
                #pragma unroll
                for (int m = 16; m > 0; m >>= 1)
                    pv += __shfl_xor_sync(0xffffffffu, pv, m);
                if (lane == 0) vsum[vt + wid + 8 * k] += pv;

                bx += dvx;
                by += dvy;
            }
            __syncthreads();   // tile reused by next stage / scratch alias
        }

        // --- u-strip reduction (scratch aliases tile region) ---
        float* scratch = (float*)tilew;
        scratch[lane * 8 + wid]        = acc0;
        scratch[(32 + lane) * 8 + wid] = acc1;
        __syncthreads();
        if (tid < TT) {
            const float* p = scratch + tid * 8;
            const float tot = ((p[0] + p[1]) + (p[2] + p[3])) +
                              ((p[4] + p[5]) + (p[6] + p[7]));
            out[((size_t)(n * Ww + (u0 + tid))) * NA + a] = tot;
        }
        __syncthreads();
    }

    // --- paired angle: sino[a+90][b] += vsum[511 - b] (2 contributors,
    //     commutative fp add -> deterministic) ---
    for (int i = tid; i < 512; i += THREADS)
        atomicAdd(&out[((size_t)(n * Ww + (511 - i))) * NA + (a + 90)],
                  vsum[i]);
}

extern "C" void kernel_launch(void* const* d_in, const int* in_sizes, int n_in,
                              void* d_out, int out_size) {
    (void)in_sizes; (void)n_in;
    const float* x = (const float*)d_in[0];
    float* out = (float*)d_out;

    cudaFuncSetAttribute(radon_kernel,
                         cudaFuncAttributeMaxDynamicSharedMemorySize,
                         SMEM_BYTES);

    cudaMemsetAsync(out, 0, (size_t)out_size * sizeof(float), 0);

    dim3 grid(90, 32, 2);   // (angle pair, image, u-half)
    radon_kernel<<<grid, THREADS, SMEM_BYTES>>>(x, out);
}

// round 10
// speedup vs baseline: 1.4247x; 1.1089x over previous
#include <cuda_runtime.h>
#include <cuda_fp16.h>
#include <cstdint>

// Radon transform, ray-driven bilinear, matching the JAX reference
// (zero-filled SMEM sampling == reference's per-corner valid masking).
//
// x: (32, 1, 512, 512) f32   ->  out: (32, 1, 512, 180) f32
//
// 90-degree symmetry (R4) + fp16 vertical-pair tile (R6) + R7 geometry
// (TV=64, 6 blocks/SM, grid 90x32x2, fixed PITCH=95 immediates).
//
// R10 change vs R7: PER-ANGLE ORIENTATION TRANSPOSE. Gather lane-stride in
// tile words is d1 = c - 95 s; at theta=43deg d1 = -64.06 = -0.06 (mod 32):
// ~30 lanes hit distinct words of ONE bank -> ~30-way LDS serialization
// (theta=20deg is ~3-way). Exact identity: running the loop with (c,s) ->
// (s,c) and vertically FLIPPED staging gives sampleT(u~,v~) =
// sample(u=v~, v=u~) (bilinear of flipped image at flipped coord is exact),
// with stride d2 = s - 95 c whose bad angles (47, 70 deg) are disjoint from
// d1's. Choose per angle by analytic resonance score; swap output roles
// (register sums -> column output, vsum -> row output). Inner loop is
// byte-identical to R7 (PITCH stays an immediate).

namespace {
constexpr int Hh = 512;
constexpr int Ww = 512;
constexpr int NA = 180;
constexpr int TT = 64;            // tile size in u and v
constexpr int PITCH = 95;         // words per pair-row (odd), cols <= 94
constexpr int PAIR_ROWS = 93;     // pair-rows <= 93
constexpr int TILE_WORDS = PAIR_ROWS * PITCH;       // 8835 half2-words
constexpr int THREADS = 256;                        // 8 warps
constexpr int SMEM_BYTES = (TILE_WORDS + 512) * 4;  // 37388 B -> 6 blocks/SM
constexpr int UT_PER_BLOCK = 4;
}

// pack two f32 into f16x2: lo = f16(lo_f) (row p), hi = f16(hi_f) (row p+1)
__device__ __forceinline__ unsigned pack_h2(float hi_f, float lo_f) {
    unsigned d;
    asm("cvt.rn.f16x2.f32 %0, %1, %2;" : "=r"(d) : "f"(hi_f), "f"(lo_f));
    return d;
}

// bank-resonance severity of lane stride delta (words): catastrophic when
// delta ~ 0 (mod 32) but |delta| >= ~2 (distinct words, one bank).
__device__ __forceinline__ int bank_score(float delta) {
    if (fabsf(delta) < 1.5f) return 0;              // broadcast: free
    const float d = fabsf(remainderf(delta, 32.0f));
    if (d < 0.75f) return 64;
    if (d < 1.5f)  return 16;
    if (d < 2.5f)  return 4;
    return 0;
}

__global__ __launch_bounds__(THREADS, 6)
void radon_kernel(const float* __restrict__ x, float* __restrict__ out) {
    extern __shared__ float sm[];
    unsigned* tilew = (unsigned*)sm;        // 8835 half2 words (aliased scratch)
    float* vsum = sm + TILE_WORDS;          // 512 floats, persistent

    const int tid  = threadIdx.x;
    const int lane = tid & 31;
    const int wid  = tid >> 5;
    const int a    = blockIdx.x;   // 0..89
    const int n    = blockIdx.y;   // 0..31
    const int z    = blockIdx.z;   // 0..1: u-half

    const float theta = (float)a * 0.017453292519943295f;
    float s0a, c0a;
    sincosf(theta, &s0a, &c0a);

    // ---- orientation choice (block-uniform, register-only) ----
    const bool T = bank_score(s0a - 95.0f * c0a) <
                   bank_score(c0a - 95.0f * s0a);
    const float c = T ? s0a : c0a;          // effective cos
    const float s = T ? c0a : s0a;          // effective sin
    const int rowStep = T ? -Ww : Ww;       // staging row direction

    const float* __restrict__ img = x + (size_t)n * (size_t)(Hh * Ww);

    // zero v-accumulator (ordered before first gather by the staging barrier)
    for (int i = tid; i < 512; i += THREADS) vsum[i] = 0.0f;

    const float dux =  32.0f * c;   // ix step per +32 u
    const float duy = -32.0f * s;   // iy step per +32 u
    const float dvx =   8.0f * s;   // ix step per +8 v
    const float dvy =   8.0f * c;   // iy step per +8 v

    for (int ut = 0; ut < UT_PER_BLOCK; ++ut) {
        const int u0 = (z * UT_PER_BLOCK + ut) * TT;
        const float fu_lo = (float)u0 - 255.5f;
        const float fu_hi = fu_lo + (float)(TT - 1);
        float acc0 = 0.f, acc1 = 0.f;

        for (int vt = 0; vt < Hh; vt += TT) {
            // --- bounding box of sample footprint for this (u,v) tile ---
            const float fv_lo = (float)vt - 255.5f;
            const float fv_hi = fv_lo + (float)(TT - 1);

            const float x00 = c * fu_lo + s * fv_lo, x01 = c * fu_lo + s * fv_hi;
            const float x10 = c * fu_hi + s * fv_lo, x11 = c * fu_hi + s * fv_hi;
            const float ixmin = fminf(fminf(x00, x01), fminf(x10, x11)) + 255.5f;
            const float ixmax = fmaxf(fmaxf(x00, x01), fmaxf(x10, x11)) + 255.5f;

            const float y00 = -s * fu_lo + c * fv_lo, y01 = -s * fu_lo + c * fv_hi;
            const float y10 = -s * fu_hi + c * fv_lo, y11 = -s * fu_hi + c * fv_hi;
            const float iymin = fminf(fminf(y00, y01), fminf(y10, y11)) + 255.5f;
            const float iymax = fmaxf(fmaxf(y00, y01), fmaxf(y10, y11)) + 255.5f;

            const int c_lo = (int)floorf(ixmin) - 1;
            const int cols = ((int)floorf(ixmax) + 2) - c_lo + 1;   // <= 94
            const int r_lo = (int)floorf(iymin) - 1;
            const int rows = ((int)floorf(iymax) + 2) - r_lo + 1;   // <= 94
            const int prs  = rows - 1;                              // <= 93

            // tile entirely outside the image -> contribution is exactly 0
            if ((c_lo >= Ww) | (r_lo >= Hh) |
                (c_lo + cols <= 0) | (r_lo + rows <= 0))
                continue;

            // per-warp contiguous pair-row block (register row-carry)
            const int npr   = (prs + 7) >> 3;
            const int pr_lo = wid * npr;
            const int pr_hi = min(pr_lo + npr, prs);

            const bool interior = (c_lo >= 0) & (c_lo + cols <= Ww) &
                                  (r_lo >= 0) & (r_lo + rows <= Hh);

            if (pr_lo < pr_hi) {
                const bool ok1 = (lane + 32 < cols);
                const bool ok2 = (lane + 64 < cols);
                if (interior) {
                    const int gr0 = r_lo + pr_lo;
                    const int fr0 = T ? (Hh - 1 - gr0) : gr0;
                    const float* srcp = img + (size_t)fr0 * Ww + c_lo + lane;
                    float p0 = srcp[0];
                    float p1 = ok1 ? srcp[32] : 0.f;
                    float p2 = ok2 ? srcp[64] : 0.f;
                    for (int pr = pr_lo; pr < pr_hi; ++pr) {
                        srcp += rowStep;
                        const float c0 = srcp[0];
                        const float c1 = ok1 ? srcp[32] : 0.f;
                        const float c2 = ok2 ? srcp[64] : 0.f;
                        unsigned* d = tilew + pr * PITCH + lane;
                        d[0] = pack_h2(c0, p0);
                        if (ok1) d[32] = pack_h2(c1, p1);
                        if (ok2) d[64] = pack_h2(c2, p2);
                        p0 = c0; p1 = c1; p2 = c2;
                    }
                } else {
                    const int g0 = c_lo + lane;
                    const int g1 = g0 + 32;
                    const int g2 = g0 + 64;
                    const bool c0ok = ((unsigned)g0 < (unsigned)Ww);
                    const bool c1ok = ok1 && ((unsigned)g1 < (unsigned)Ww);
                    const bool c2ok = ok2 && ((unsigned)g2 < (unsigned)Ww);
                    const int gc0 = min(max(g0, 0), Ww - 1);
                    const int gc1 = min(max(g1, 0), Ww - 1);
                    const int gc2 = min(max(g2, 0), Ww - 1);

                    int gr = r_lo + pr_lo;
                    bool rok = ((unsigned)gr < (unsigned)Hh);
                    int grc = min(max(gr, 0), Hh - 1);
                    const float* srcp =
                        img + (size_t)(T ? (Hh - 1 - grc) : grc) * Ww;
                    float p0 = (rok & c0ok) ? srcp[gc0] : 0.f;
                    float p1 = (rok & c1ok) ? srcp[gc1] : 0.f;
                    float p2 = (rok & c2ok) ? srcp[gc2] : 0.f;
                    for (int pr = pr_lo; pr < pr_hi; ++pr) {
                        gr = r_lo + pr + 1;
                        rok = ((unsigned)gr < (unsigned)Hh);
                        grc = min(max(gr, 0), Hh - 1);
                        srcp = img + (size_t)(T ? (Hh - 1 - grc) : grc) * Ww;
                        const float c0 = (rok & c0ok) ? srcp[gc0] : 0.f;
                        const float c1 = (rok & c1ok) ? srcp[gc1] : 0.f;
                        const float c2 = (rok & c2ok) ? srcp[gc2] : 0.f;
                        unsigned* d = tilew + pr * PITCH + lane;
                        d[0] = pack_h2(c0, p0);
                        if (ok1) d[32] = pack_h2(c1, p1);
                        if (ok2) d[64] = pack_h2(c2, p2);
                        p0 = c0; p1 = c1; p2 = c2;
                    }
                }
            }
            __syncthreads();

            // --- gather + bilinear: warp wid handles v = vt + wid + 8k ---
            const __half2* tp = (const __half2*)tilew;
            const float fu = (float)(u0 + lane) - 255.5f;
            const float fv = (float)(vt + wid) - 255.5f;
            float bx = fmaf(c, fu, fmaf(s, fv, 255.5f)) - (float)c_lo;
            float by = fmaf(-s, fu, fmaf(c, fv, 255.5f)) - (float)r_lo;

            #pragma unroll
            for (int k = 0; k < 8; ++k) {
                float s0, s1;
                {   // u = u0 + lane
                    const float fx0 = floorf(bx);
                    const float fy0 = floorf(by);
                    const float fx = bx - fx0;
                    const float fy = by - fy0;
                    const int idx = (int)fmaf(fy0, (float)PITCH, fx0);
                    const __half2 w0 = tp[idx];       // (v00, v10)
                    const __half2 w1 = tp[idx + 1];   // (v01, v11)
                    const __half2 fx2 = __float2half2_rn(fx);
                    const __half2 tb = __hfma2(fx2, __hsub2(w1, w0), w0);
                    const float top = __low2float(tb);
                    const float bot = __high2float(tb);
                    s0 = fmaf(fy, bot - top, top);
                }
                {   // u = u0 + 32 + lane
                    const float ix = bx + dux;
                    const float iy = by + duy;
                    const float fx0 = floorf(ix);
                    const float fy0 = floorf(iy);
                    const float fx = ix - fx0;
                    const float fy = iy - fy0;
                    const int idx = (int)fmaf(fy0, (float)PITCH, fx0);
                    const __half2 w0 = tp[idx];
                    const __half2 w1 = tp[idx + 1];
                    const __half2 fx2 = __float2half2_rn(fx);
                    const __half2 tb = __hfma2(fx2, __hsub2(w1, w0), w0);
                    const float top = __low2float(tb);
                    const float bot = __high2float(tb);
                    s1 = fmaf(fy, bot - top, top);
                }
                acc0 += s0;
                acc1 += s1;

                // sum across the 64 internal-u's at internal-v = vt+wid+8k
                float pv = s0 + s1;
                #pragma unroll
                for (int m = 16; m > 0; m >>= 1)
                    pv += __shfl_xor_sync(0xffffffffu, pv, m);
                if (lane == 0) vsum[vt + wid + 8 * k] += pv;

                bx += dvx;
                by += dvy;
            }
            __syncthreads();   // tile reused by next stage / scratch alias
        }

        // --- per-internal-u reduction (scratch aliases tile region) ---
        // normal:     acc(u)  = row sum    -> out[.., u, a]
        // transposed: acc(u~) = column sum -> out[.., 511-u~, a+90]
        float* scratch = (float*)tilew;
        scratch[lane * 8 + wid]        = acc0;
        scratch[(32 + lane) * 8 + wid] = acc1;
        __syncthreads();
        if (tid < TT) {
            const float* p = scratch + tid * 8;
            const float tot = ((p[0] + p[1]) + (p[2] + p[3])) +
                              ((p[4] + p[5]) + (p[6] + p[7]));
            const int uu  = u0 + tid;
            const int row = T ? (Hh - 1 - uu) : uu;
            const int ang = T ? (a + 90) : a;
            atomicAdd(&out[((size_t)(n * Ww + row)) * NA + ang], tot);
        }
        __syncthreads();
    }

    // --- internal-v sums ---
    // normal:     vsum(v)  = column sum -> out[.., 511-v, a+90]
    // transposed: vsum(v~) = row sum    -> out[.., v~, a]
    {
        const int ang = T ? a : (a + 90);
        for (int i = tid; i < 512; i += THREADS) {
            const int row = T ? i : (Hh - 1 - i);
            atomicAdd(&out[((size_t)(n * Ww + row)) * NA + ang], vsum[i]);
        }
    }
}

extern "C" void kernel_launch(void* const* d_in, const int* in_sizes, int n_in,
                              void* d_out, int out_size) {
    (void)in_sizes; (void)n_in;
    const float* x = (const float*)d_in[0];
    float* out = (float*)d_out;

    cudaFuncSetAttribute(radon_kernel,
                         cudaFuncAttributeMaxDynamicSharedMemorySize,
                         SMEM_BYTES);

    cudaMemsetAsync(out, 0, (size_t)out_size * sizeof(float), 0);

    dim3 grid(90, 32, 2);   // (angle pair, image, u-half)
    radon_kernel<<<grid, THREADS, SMEM_BYTES>>>(x, out);
}

// round 11
// speedup vs baseline: 1.6799x; 1.1792x over previous
#include <cuda_runtime.h>
#include <cuda_fp16.h>
#include <cstdint>

// Radon transform, ray-driven bilinear, matching the JAX reference
// (zero-padded sampling == reference's per-corner valid masking).
//
// x: (32, 1, 512, 512) f32   ->  out: (32, 1, 512, 180) f32
//
// R11 structure:
//  - prep kernel: padded (704x704) fp16 VERTICAL-PAIR image per batch in a
//    __device__ global (60.5MB, L2-resident). word(p,c) = half2(row p, p+1),
//    zero outside the 512x512 interior.
//  - main kernel staging: unconditional LDG.128+STS.128 of pair words
//    (no conversion, no bounds branches — padding absorbs OOB).
//  - PITCH=96 (=0 mod 32): gather bank = fx0 mod 32 only; combined with
//    reflection transpose T <=> s>c (ix lane-stride = max(c,s) >= 0.71)
//    -> <=2-way LDS conflicts at every angle.
//  - chunk-2 butterfly v-reduce: 5 SHFL per 2 k (was 10) + half the RMWs.
//  - 90-deg symmetry (R4), output mapping identical to R10 (verified):
//    normal: acc(u)->out[u][a], vsum(v)->out[511-v][a+90]
//    T:      acc(u~)->out[511-u~][a+90], vsum(v~)->out[v~][a]

namespace {
constexpr int Hh = 512;
constexpr int Ww = 512;
constexpr int NA = 180;
constexpr int PAD = 96;
constexpr int PDIM = 704;               // 512 + 2*96
constexpr int PWORDS = PDIM * PDIM;     // per-image pair words
constexpr int PITCH = 96;               // tile words per pair-row
constexpr int MAXPR = 93;               // max pair-rows per tile
constexpr int TILE_WORDS = MAXPR * PITCH;             // 8928
constexpr int THREADS = 256;                          // 8 warps
constexpr int SMEM_BYTES = (TILE_WORDS + 512) * 4;    // 37760 -> 6 blocks/SM
constexpr int UT_PER_BLOCK = 4;
}

__device__ __align__(16) unsigned g_pairs[32ull * PWORDS];  // 60.5 MB

// pack two f32 into f16x2: low half = lo_f (row p), high half = hi_f (row p+1)
__device__ __forceinline__ unsigned pack_h2(float hi_f, float lo_f) {
    unsigned d;
    asm("cvt.rn.f16x2.f32 %0, %1, %2;" : "=r"(d) : "f"(hi_f), "f"(lo_f));
    return d;
}

__global__ __launch_bounds__(256, 8)
void prep_pairs(const float* __restrict__ x) {
    const int n = blockIdx.y;
    const int idx = blockIdx.x * 256 + threadIdx.x;
    if (idx >= PWORDS) return;
    const int prow = idx / PDIM;
    const int pcol = idx - prow * PDIM;
    const int r0 = prow - PAD;
    const int cc = pcol - PAD;
    const float* img = x + (size_t)n * (Hh * Ww);
    float lo = 0.f, hi = 0.f;
    if ((unsigned)cc < (unsigned)Ww) {
        if ((unsigned)r0 < (unsigned)Hh)       lo = img[r0 * Ww + cc];
        if ((unsigned)(r0 + 1) < (unsigned)Hh) hi = img[(r0 + 1) * Ww + cc];
    }
    g_pairs[(size_t)n * PWORDS + idx] = pack_h2(hi, lo);
}

__global__ __launch_bounds__(THREADS, 6)
void radon_kernel(float* __restrict__ out) {
    extern __shared__ float sm[];
    unsigned* tilew = (unsigned*)sm;        // 8928 words (aliased scratch)
    float* vsum = sm + TILE_WORDS;          // 512 floats, persistent

    const int tid  = threadIdx.x;
    const int lane = tid & 31;
    const int wid  = tid >> 5;
    const int a    = blockIdx.x;   // 0..89
    const int n    = blockIdx.y;   // 0..31
    const int z    = blockIdx.z;   // 0..1: u-half

    const float theta = (float)a * 0.017453292519943295f;
    float s0, c0;
    sincosf(theta, &s0, &c0);

    // reflection transpose: keep ix lane-stride = max(c0,s0)
    const bool T = (s0 > c0);
    const float A = T ? s0 : c0;            // d(ix)/dfu
    const float B = T ? c0 : s0;            // d(ix)/dfv
    const float sg = T ? -1.0f : 1.0f;      // iy = sg*(-B*fu + A*fv) + 255.5

    const unsigned* __restrict__ gp = g_pairs + (size_t)n * PWORDS;

    for (int i = tid; i < 512; i += THREADS) vsum[i] = 0.0f;

    const float dux = 32.0f * A;            // ix step per +32 u
    const float duy = -32.0f * B * sg;      // iy step per +32 u
    const float dvx =  8.0f * B;            // ix step per +8 v
    const float dvy =  8.0f * A * sg;       // iy step per +8 v

    for (int ut = 0; ut < UT_PER_BLOCK; ++ut) {
        const int u0 = (z * UT_PER_BLOCK + ut) * 64;
        const float fu_lo = (float)u0 - 255.5f;
        const float fu_hi = fu_lo + 63.0f;
        float acc0 = 0.f, acc1 = 0.f;

        for (int vt = 0; vt < Hh; vt += 64) {
            const float fv_lo = (float)vt - 255.5f;
            const float fv_hi = fv_lo + 63.0f;

            // ix monotone in fu,fv (A,B >= 0)
            const float ixmin = fmaf(A, fu_lo, fmaf(B, fv_lo, 255.5f));
            const float ixmax = fmaf(A, fu_hi, fmaf(B, fv_hi, 255.5f));
            // iy = sg*p + 255.5, p = -B*fu + A*fv
            const float pmin = fmaf(-B, fu_hi, A * fv_lo);
            const float pmax = fmaf(-B, fu_lo, A * fv_hi);
            const float q0 = sg * pmin, q1 = sg * pmax;
            const float iymin = 255.5f + fminf(q0, q1);
            const float iymax = 255.5f + fmaxf(q0, q1);

            const int c_lo = (int)floorf(ixmin) - 1;
            const int cols = (int)floorf(ixmax) - c_lo + 2;   // <= 93
            const int r_lo = (int)floorf(iymin) - 1;
            const int prs  = (int)floorf(iymax) - r_lo + 2;   // <= 93

            // tile entirely outside the image -> contribution exactly 0
            if ((c_lo >= Ww) | (r_lo >= Hh) |
                (c_lo + cols <= 0) | (r_lo + prs + 1 <= 0))
                continue;

            const int cs = c_lo & ~3;       // 16B-aligned staging origin

            // --- stage pair words: LDG.128 + STS.128, 96 words/pair-row ---
            {
                const uint4* gsrc = (const uint4*)
                    (gp + (size_t)(r_lo + PAD + wid) * PDIM + (cs + PAD));
                uint4* dst = (uint4*)(tilew + wid * PITCH);
                for (int pr = wid; pr < prs; pr += 8) {
                    if (lane < 24) dst[lane] = __ldg(gsrc + lane);
                    gsrc += 2 * PDIM;       // 8 rows of PDIM/4 uint4
                    dst  += 2 * PITCH / 1;  // 8 rows * 96 words / 4 per uint4
                }
            }
            __syncthreads();

            // --- gather + bilinear: warp wid handles v = vt + wid + 8k ---
            const __half2* tp = (const __half2*)tilew;
            const float fu = (float)(u0 + lane) - 255.5f;
            const float fv = (float)(vt + wid) - 255.5f;
            float bx = fmaf(A, fu, fmaf(B, fv, 255.5f)) - (float)cs;
            float by = sg * fmaf(-B, fu, A * fv) + 255.5f - (float)r_lo;

            float pv0 = 0.f;
            #pragma unroll
            for (int k = 0; k < 8; ++k) {
                float s0v, s1v;
                {   // u = u0 + lane
                    const float fx0 = floorf(bx);
                    const float fy0 = floorf(by);
                    const float fx = bx - fx0;
                    const float fy = by - fy0;
                    const int idx = (int)fmaf(fy0, (float)PITCH, fx0);
                    const __half2 w0 = tp[idx];       // (top, bot)
                    const __half2 w1 = tp[idx + 1];
                    const __half2 fx2 = __float2half2_rn(fx);
                    const __half2 tb = __hfma2(fx2, __hsub2(w1, w0), w0);
                    const float top = __low2float(tb);
                    const float bot = __high2float(tb);
                    s0v = fmaf(fy, bot - top, top);
                }
                {   // u = u0 + 32 + lane
                    const float ix = bx + dux;
                    const float iy = by + duy;
                    const float fx0 = floorf(ix);
                    const float fy0 = floorf(iy);
                    const float fx = ix - fx0;
                    const float fy = iy - fy0;
                    const int idx = (int)fmaf(fy0, (float)PITCH, fx0);
                    const __half2 w0 = tp[idx];
                    const __half2 w1 = tp[idx + 1];
                    const __half2 fx2 = __float2half2_rn(fx);
                    const __half2 tb = __hfma2(fx2, __hsub2(w1, w0), w0);
                    const float top = __low2float(tb);
                    const float bot = __high2float(tb);
                    s1v = fmaf(fy, bot - top, top);
                }
                acc0 += s0v;
                acc1 += s1v;

                const float pv = s0v + s1v;
                if ((k & 1) == 0) {
                    pv0 = pv;
                } else {
                    // chunk-2 butterfly: lanes<16 sum pv0, lanes>=16 sum pv1
                    float xs = (lane & 16) ? pv0 : pv;
                    xs = __shfl_xor_sync(0xffffffffu, xs, 16);
                    float val = ((lane & 16) ? pv : pv0) + xs;
                    val += __shfl_xor_sync(0xffffffffu, val, 8);
                    val += __shfl_xor_sync(0xffffffffu, val, 4);
                    val += __shfl_xor_sync(0xffffffffu, val, 2);
                    val += __shfl_xor_sync(0xffffffffu, val, 1);
                    if ((lane & 15) == 0)
                        vsum[vt + wid + 8 * (k - 1) + ((lane >> 4) << 3)] += val;
                }

                bx += dvx;
                by += dvy;
            }
            __syncthreads();   // tile reused by next stage / scratch alias
        }

        // --- per-internal-u reduction (scratch aliases tile region) ---
        float* scratch = (float*)tilew;
        scratch[lane * 8 + wid]        = acc0;
        scratch[(32 + lane) * 8 + wid] = acc1;
        __syncthreads();
        if (tid < 64) {
            const float* p = scratch + tid * 8;
            const float tot = ((p[0] + p[1]) + (p[2] + p[3])) +
                              ((p[4] + p[5]) + (p[6] + p[7]));
            const int uu  = u0 + tid;
            const int row = T ? (Hh - 1 - uu) : uu;
            const int ang = T ? (a + 90) : a;
            atomicAdd(&out[((size_t)(n * Ww + row)) * NA + ang], tot);
        }
        __syncthreads();
    }

    // --- internal-v sums (2 u-half contributors -> deterministic) ---
    {
        const int ang = T ? a : (a + 90);
        for (int i = tid; i < 512; i += THREADS) {
            const int row = T ? i : (Hh - 1 - i);
            atomicAdd(&out[((size_t)(n * Ww + row)) * NA + ang], vsum[i]);
        }
    }
}

extern "C" void kernel_launch(void* const* d_in, const int* in_sizes, int n_in,
                              void* d_out, int out_size) {
    (void)in_sizes; (void)n_in;
    const float* x = (const float*)d_in[0];
    float* out = (float*)d_out;

    cudaFuncSetAttribute(radon_kernel,
                         cudaFuncAttributeMaxDynamicSharedMemorySize,
                         SMEM_BYTES);

    cudaMemsetAsync(out, 0, (size_t)out_size * sizeof(float), 0);

    dim3 pgrid((PWORDS + 255) / 256, 32);
    prep_pairs<<<pgrid, 256>>>(x);

    dim3 grid(90, 32, 2);   // (angle pair, image, u-half)
    radon_kernel<<<grid, THREADS, SMEM_BYTES>>>(out);
}

// round 12
// speedup vs baseline: 1.7222x; 1.0252x over previous
#include <cuda_runtime.h>
#include <cuda_fp16.h>
#include <cstdint>

// Radon transform, ray-driven bilinear, matching the JAX reference
// (zero-padded sampling == reference's per-corner valid masking).
//
// x: (32, 1, 512, 512) f32   ->  out: (32, 1, 512, 180) f32
//
// R11 base:
//  - prep kernel: padded (704x704) fp16 VERTICAL-PAIR image per batch in a
//    __device__ global (60.5MB, L2-resident); zero outside 512x512.
//  - staging: unconditional LDG.128+STS.128 (padding absorbs OOB).
//  - PITCH=96 (=0 mod 32) + reflection transpose T <=> s>c: bank = fx0 mod 32,
//    lane stride max(c,s)>=0.71 -> <=2-way LDS conflicts everywhere.
//  - 90-deg symmetry: normal pass -> out[u][a] and out[511-v][a+90];
//    T pass -> out[511-u~][a+90] and out[v~][a].
//
// R12 changes (L1-wavefront bound: staging 60 wf, SHFL 20 wf per warp-tile):
//  - narrow staging: stage only nvec = ceil((c_lo+cols-cs)/4) uint4 lanes
//    (was fixed 24) -> -12..17% staging wavefronts.
//  - chunk-4 butterfly v-reduce: 6 SHFL per 4 k (was 10 per 4 k), half RMWs.

namespace {
constexpr int Hh = 512;
constexpr int Ww = 512;
constexpr int NA = 180;
constexpr int PAD = 96;
constexpr int PDIM = 704;               // 512 + 2*96
constexpr int PWORDS = PDIM * PDIM;     // per-image pair words
constexpr int PITCH = 96;               // tile words per pair-row
constexpr int MAXPR = 93;               // max pair-rows per tile
constexpr int TILE_WORDS = MAXPR * PITCH;             // 8928
constexpr int THREADS = 256;                          // 8 warps
constexpr int SMEM_BYTES = (TILE_WORDS + 512) * 4;    // 37760 -> 6 blocks/SM
constexpr int UT_PER_BLOCK = 4;
}

__device__ __align__(16) unsigned g_pairs[32ull * PWORDS];  // 60.5 MB

// pack two f32 into f16x2: low half = lo_f (row p), high half = hi_f (row p+1)
__device__ __forceinline__ unsigned pack_h2(float hi_f, float lo_f) {
    unsigned d;
    asm("cvt.rn.f16x2.f32 %0, %1, %2;" : "=r"(d) : "f"(hi_f), "f"(lo_f));
    return d;
}

__global__ __launch_bounds__(256, 8)
void prep_pairs(const float* __restrict__ x) {
    const int n = blockIdx.y;
    const int idx = blockIdx.x * 256 + threadIdx.x;
    if (idx >= PWORDS) return;
    const int prow = idx / PDIM;
    const int pcol = idx - prow * PDIM;
    const int r0 = prow - PAD;
    const int cc = pcol - PAD;
    const float* img = x + (size_t)n * (Hh * Ww);
    float lo = 0.f, hi = 0.f;
    if ((unsigned)cc < (unsigned)Ww) {
        if ((unsigned)r0 < (unsigned)Hh)       lo = img[r0 * Ww + cc];
        if ((unsigned)(r0 + 1) < (unsigned)Hh) hi = img[(r0 + 1) * Ww + cc];
    }
    g_pairs[(size_t)n * PWORDS + idx] = pack_h2(hi, lo);
}

__global__ __launch_bounds__(THREADS, 6)
void radon_kernel(float* __restrict__ out) {
    extern __shared__ float sm[];
    unsigned* tilew = (unsigned*)sm;        // 8928 words (aliased scratch)
    float* vsum = sm + TILE_WORDS;          // 512 floats, persistent

    const int tid  = threadIdx.x;
    const int lane = tid & 31;
    const int wid  = tid >> 5;
    const int a    = blockIdx.x;   // 0..89
    const int n    = blockIdx.y;   // 0..31
    const int z    = blockIdx.z;   // 0..1: u-half

    const float theta = (float)a * 0.017453292519943295f;
    float s0, c0;
    sincosf(theta, &s0, &c0);

    // reflection transpose: keep ix lane-stride = max(c0,s0)
    const bool T = (s0 > c0);
    const float A = T ? s0 : c0;            // d(ix)/dfu
    const float B = T ? c0 : s0;            // d(ix)/dfv
    const float sg = T ? -1.0f : 1.0f;      // iy = sg*(-B*fu + A*fv) + 255.5

    const unsigned* __restrict__ gp = g_pairs + (size_t)n * PWORDS;

    for (int i = tid; i < 512; i += THREADS) vsum[i] = 0.0f;

    const float dux = 32.0f * A;            // ix step per +32 u
    const float duy = -32.0f * B * sg;      // iy step per +32 u
    const float dvx =  8.0f * B;            // ix step per +8 v
    const float dvy =  8.0f * A * sg;       // iy step per +8 v

    for (int ut = 0; ut < UT_PER_BLOCK; ++ut) {
        const int u0 = (z * UT_PER_BLOCK + ut) * 64;
        const float fu_lo = (float)u0 - 255.5f;
        const float fu_hi = fu_lo + 63.0f;
        float acc0 = 0.f, acc1 = 0.f;

        for (int vt = 0; vt < Hh; vt += 64) {
            const float fv_lo = (float)vt - 255.5f;
            const float fv_hi = fv_lo + 63.0f;

            // ix monotone in fu,fv (A,B >= 0)
            const float ixmin = fmaf(A, fu_lo, fmaf(B, fv_lo, 255.5f));
            const float ixmax = fmaf(A, fu_hi, fmaf(B, fv_hi, 255.5f));
            // iy = sg*p + 255.5, p = -B*fu + A*fv
            const float pmin = fmaf(-B, fu_hi, A * fv_lo);
            const float pmax = fmaf(-B, fu_lo, A * fv_hi);
            const float q0 = sg * pmin, q1 = sg * pmax;
            const float iymin = 255.5f + fminf(q0, q1);
            const float iymax = 255.5f + fmaxf(q0, q1);

            const int c_lo = (int)floorf(ixmin) - 1;
            const int cols = (int)floorf(ixmax) - c_lo + 2;   // <= 93
            const int r_lo = (int)floorf(iymin) - 1;
            const int prs  = (int)floorf(iymax) - r_lo + 2;   // <= 93

            // tile entirely outside the image -> contribution exactly 0
            if ((c_lo >= Ww) | (r_lo >= Hh) |
                (c_lo + cols <= 0) | (r_lo + prs + 1 <= 0))
                continue;

            const int cs = c_lo & ~3;       // 16B-aligned staging origin
            const int nvec = (c_lo + cols - cs + 3) >> 2;   // <= 24 uint4

            // --- stage pair words: LDG.128 + STS.128, nvec uint4/pair-row ---
            {
                const uint4* gsrc = (const uint4*)
                    (gp + (size_t)(r_lo + PAD + wid) * PDIM + (cs + PAD));
                uint4* dst = (uint4*)(tilew + wid * PITCH);
                for (int pr = wid; pr < prs; pr += 8) {
                    if (lane < nvec) dst[lane] = __ldg(gsrc + lane);
                    gsrc += 2 * PDIM;       // 8 pair-rows
                    dst  += 2 * PITCH;      // 8 * 96 words / 4 per uint4
                }
            }
            __syncthreads();

            // --- gather + bilinear: warp wid handles v = vt + wid + 8k ---
            const __half2* tp = (const __half2*)tilew;
            const float fu = (float)(u0 + lane) - 255.5f;
            const float fv = (float)(vt + wid) - 255.5f;
            float bx = fmaf(A, fu, fmaf(B, fv, 255.5f)) - (float)cs;
            float by = sg * fmaf(-B, fu, A * fv) + 255.5f - (float)r_lo;

            float p0, p1, p2;
            #pragma unroll
            for (int k = 0; k < 8; ++k) {
                float s0v, s1v;
                {   // u = u0 + lane
                    const float fx0 = floorf(bx);
                    const float fy0 = floorf(by);
                    const float fx = bx - fx0;
                    const float fy = by - fy0;
                    const int idx = (int)fmaf(fy0, (float)PITCH, fx0);
                    const __half2 w0 = tp[idx];       // (top, bot)
                    const __half2 w1 = tp[idx + 1];
                    const __half2 fx2 = __float2half2_rn(fx);
                    const __half2 tb = __hfma2(fx2, __hsub2(w1, w0), w0);
                    const float top = __low2float(tb);
                    const float bot = __high2float(tb);
                    s0v = fmaf(fy, bot - top, top);
                }
                {   // u = u0 + 32 + lane
                    const float ix = bx + dux;
                    const float iy = by + duy;
                    const float fx0 = floorf(ix);
                    const float fy0 = floorf(iy);
                    const float fx = ix - fx0;
                    const float fy = iy - fy0;
                    const int idx = (int)fmaf(fy0, (float)PITCH, fx0);
                    const __half2 w0 = tp[idx];
                    const __half2 w1 = tp[idx + 1];
                    const __half2 fx2 = __float2half2_rn(fx);
                    const __half2 tb = __hfma2(fx2, __hsub2(w1, w0), w0);
                    const float top = __low2float(tb);
                    const float bot = __high2float(tb);
                    s1v = fmaf(fy, bot - top, top);
                }
                acc0 += s0v;
                acc1 += s1v;

                const float pv = s0v + s1v;
                const int km = k & 3;
                if (km == 0) p0 = pv;
                else if (km == 1) p1 = pv;
                else if (km == 2) p2 = pv;
                else {
                    // chunk-4 butterfly: lane-group g (of 8) sums p_g
                    float x0 = (lane & 16) ? p0 : p2;
                    x0 = __shfl_xor_sync(0xffffffffu, x0, 16);
                    const float f0 = ((lane & 16) ? p2 : p0) + x0;
                    float x1 = (lane & 16) ? p1 : pv;
                    x1 = __shfl_xor_sync(0xffffffffu, x1, 16);
                    const float f1 = ((lane & 16) ? pv : p1) + x1;
                    float y = (lane & 8) ? f0 : f1;
                    y = __shfl_xor_sync(0xffffffffu, y, 8);
                    float r = ((lane & 8) ? f1 : f0) + y;
                    r += __shfl_xor_sync(0xffffffffu, r, 4);
                    r += __shfl_xor_sync(0xffffffffu, r, 2);
                    r += __shfl_xor_sync(0xffffffffu, r, 1);
                    if ((lane & 7) == 0)
                        vsum[vt + wid + 8 * (k - 3 + (lane >> 3))] += r;
                }

                bx += dvx;
                by += dvy;
            }
            __syncthreads();   // tile reused by next stage / scratch alias
        }

        // --- per-internal-u reduction (scratch aliases tile region) ---
        float* scratch = (float*)tilew;
        scratch[lane * 8 + wid]        = acc0;
        scratch[(32 + lane) * 8 + wid] = acc1;
        __syncthreads();
        if (tid < 64) {
            const float* p = scratch + tid * 8;
            const float tot = ((p[0] + p[1]) + (p[2] + p[3])) +
                              ((p[4] + p[5]) + (p[6] + p[7]));
            const int uu  = u0 + tid;
            const int row = T ? (Hh - 1 - uu) : uu;
            const int ang = T ? (a + 90) : a;
            atomicAdd(&out[((size_t)(n * Ww + row)) * NA + ang], tot);
        }
        __syncthreads();
    }

    // --- internal-v sums (2 u-half contributors -> deterministic) ---
    {
        const int ang = T ? a : (a + 90);
        for (int i = tid; i < 512; i += THREADS) {
            const int row = T ? i : (Hh - 1 - i);
            atomicAdd(&out[((size_t)(n * Ww + row)) * NA + ang], vsum[i]);
        }
    }
}

extern "C" void kernel_launch(void* const* d_in, const int* in_sizes, int n_in,
                              void* d_out, int out_size) {
    (void)in_sizes; (void)n_in;
    const float* x = (const float*)d_in[0];
    float* out = (float*)d_out;

    cudaFuncSetAttribute(radon_kernel,
                         cudaFuncAttributeMaxDynamicSharedMemorySize,
                         SMEM_BYTES);

    cudaMemsetAsync(out, 0, (size_t)out_size * sizeof(float), 0);

    dim3 pgrid((PWORDS + 255) / 256, 32);
    prep_pairs<<<pgrid, 256>>>(x);

    dim3 grid(90, 32, 2);   // (angle pair, image, u-half)
    radon_kernel<<<grid, THREADS, SMEM_BYTES>>>(out);
}

// round 13
// speedup vs baseline: 2.4267x; 1.4091x over previous
#include <cuda_runtime.h>
#include <cuda_fp16.h>
#include <cstdint>

// Radon transform, ray-driven bilinear, matching the JAX reference
// (zero-padded sampling == reference's per-corner valid masking).
//
// x: (32, 1, 512, 512) f32   ->  out: (32, 1, 512, 180) f32
//
// R13: BATCH-PAIRED tiles. word(r,c) = half2(img_{2n}[r][c], img_{2n+1}[r][c])
// in a padded 704x704 image (zero outside 512x512; 16 pairs, 31.7MB, L2-res).
// One staged tile + ONE set of address math serves BOTH images; bilinear is
// full half2 SIMD (both images at once). Staging bytes and barriers per
// image-sample halve; gather instrs/sample ~ -40%.
//  - PITCH=96 (=0 mod 32) + reflection transpose T <=> s>c: <=2-way LDS
//    conflicts at every angle (w10/w11 are separate LDS instructions).
//  - 90-deg symmetry: normal: acc(u)->out[u][a], vsum(v)->out[511-v][a+90];
//    T: acc(u~)->out[511-u~][a+90], vsum(v~)->out[v~][a].
//  - grid (90,16,4): z = (u-half, v-half); every output gets exactly TWO
//    atomicAdd contributors (commutative -> deterministic).

namespace {
constexpr int Hh = 512;
constexpr int Ww = 512;
constexpr int NA = 180;
constexpr int PAD = 96;
constexpr int PDIM = 704;                 // 512 + 2*96
constexpr int PWORDS = PDIM * PDIM;       // per-pair words
constexpr int PITCH = 96;                 // tile words per row (0 mod 32)
constexpr int MAXROWS = 94;               // rows per tile <= 94
constexpr int TILE_WORDS = MAXROWS * PITCH;           // 9024
constexpr int THREADS = 256;                          // 8 warps
constexpr int VS = 256;                               // v-half extent
constexpr int SMEM_BYTES = (TILE_WORDS + 2 * VS) * 4; // 38144 -> 5 blocks/SM
}

__device__ __align__(16) unsigned g_pairs[16ull * PWORDS];  // 31.7 MB

// pack two f32 into f16x2: high <- a, low <- b
__device__ __forceinline__ unsigned pack_h2(float a_hi, float b_lo) {
    unsigned d;
    asm("cvt.rn.f16x2.f32 %0, %1, %2;" : "=r"(d) : "f"(a_hi), "f"(b_lo));
    return d;
}

__global__ __launch_bounds__(256, 8)
void prep_pairs(const float* __restrict__ x) {
    const int np = blockIdx.y;            // 0..15
    const int idx = blockIdx.x * 256 + threadIdx.x;
    if (idx >= PWORDS) return;
    const int prow = idx / PDIM;
    const int pcol = idx - prow * PDIM;
    const int r = prow - PAD;
    const int cc = pcol - PAD;
    float va = 0.f, vb = 0.f;
    if (((unsigned)r < (unsigned)Hh) & ((unsigned)cc < (unsigned)Ww)) {
        va = x[((size_t)(2 * np) * Hh + r) * Ww + cc];
        vb = x[((size_t)(2 * np + 1) * Hh + r) * Ww + cc];
    }
    // low half = image 2np, high half = image 2np+1
    g_pairs[(size_t)np * PWORDS + idx] = pack_h2(vb, va);
}

__global__ __launch_bounds__(THREADS, 5)
void radon_kernel(float* __restrict__ out) {
    extern __shared__ float sm[];
    unsigned* tilew = (unsigned*)sm;        // 9024 words (aliased scratch)
    float* vsumA = sm + TILE_WORDS;         // 256 floats
    float* vsumB = vsumA + VS;              // 256 floats

    const int tid  = threadIdx.x;
    const int lane = tid & 31;
    const int wid  = tid >> 5;
    const int a    = blockIdx.x;   // 0..89
    const int np   = blockIdx.y;   // 0..15 (image pair)
    const int zu   = blockIdx.z & 1;
    const int zv   = blockIdx.z >> 1;
    const int v_base = zv * VS;

    const float theta = (float)a * 0.017453292519943295f;
    float s0, c0;
    sincosf(theta, &s0, &c0);

    // reflection transpose: keep ix lane-stride = max(c0,s0) >= 0.71
    const bool T = (s0 > c0);
    const float A = T ? s0 : c0;            // d(ix)/dfu
    const float B = T ? c0 : s0;            // d(ix)/dfv
    const float sg = T ? -1.0f : 1.0f;      // iy = sg*(-B*fu + A*fv) + 255.5

    const unsigned* __restrict__ gp = g_pairs + (size_t)np * PWORDS;

    for (int i = tid; i < 2 * VS; i += THREADS) vsumA[i] = 0.0f;

    const float dux = 32.0f * A;            // ix step per +32 u
    const float duy = -32.0f * B * sg;      // iy step per +32 u
    const float dvx =  8.0f * B;            // ix step per +8 v
    const float dvy =  8.0f * A * sg;       // iy step per +8 v

    for (int ut = 0; ut < 4; ++ut) {
        const int u0 = (zu * 4 + ut) * 64;
        const float fu_lo = (float)u0 - 255.5f;
        const float fu_hi = fu_lo + 63.0f;
        float accA0 = 0.f, accA1 = 0.f, accB0 = 0.f, accB1 = 0.f;

        for (int vti = 0; vti < 4; ++vti) {
            const int vt = v_base + vti * 64;
            const float fv_lo = (float)vt - 255.5f;
            const float fv_hi = fv_lo + 63.0f;

            // ix monotone (A,B >= 0); iy = sg*p + 255.5
            const float ixmin = fmaf(A, fu_lo, fmaf(B, fv_lo, 255.5f));
            const float ixmax = fmaf(A, fu_hi, fmaf(B, fv_hi, 255.5f));
            const float pmin = fmaf(-B, fu_hi, A * fv_lo);
            const float pmax = fmaf(-B, fu_lo, A * fv_hi);
            const float q0 = sg * pmin, q1 = sg * pmax;
            const float iymin = 255.5f + fminf(q0, q1);
            const float iymax = 255.5f + fmaxf(q0, q1);

            const int c_lo = (int)floorf(ixmin) - 1;
            const int cols = (int)floorf(ixmax) - c_lo + 2;   // <= 93
            const int r_lo = (int)floorf(iymin) - 1;
            const int rows = (int)floorf(iymax) - r_lo + 3;   // <= 94

            // tile entirely outside the image -> contribution exactly 0
            if ((c_lo >= Ww) | (r_lo >= Hh) |
                (c_lo + cols <= 0) | (r_lo + rows <= 0))
                continue;

            const int cs = c_lo & ~3;       // 16B-aligned staging origin
            const int nvec = (c_lo + cols - cs + 3) >> 2;   // <= 24 uint4

            // --- stage rows: LDG.128 + STS.128, nvec uint4 per row ---
            {
                const uint4* gsrc = (const uint4*)
                    (gp + (size_t)(r_lo + PAD + wid) * PDIM + (cs + PAD));
                uint4* dst = (uint4*)(tilew + wid * PITCH);
                for (int r = wid; r < rows; r += 8) {
                    if (lane < nvec) dst[lane] = __ldg(gsrc + lane);
                    gsrc += 2 * PDIM;
                    dst  += 2 * PITCH;
                }
            }
            __syncthreads();

            // --- gather: full half2 bilinear, BOTH images per LDS set ---
            const __half2* tp = (const __half2*)tilew;
            const float fu = (float)(u0 + lane) - 255.5f;
            const float fv = (float)(vt + wid) - 255.5f;
            float bx = fmaf(A, fu, fmaf(B, fv, 255.5f)) - (float)cs;
            float by = sg * fmaf(-B, fu, A * fv) + 255.5f - (float)r_lo;

            float pA0, pB0;
            #pragma unroll
            for (int k = 0; k < 8; ++k) {
                float sA, sB;   // sample sums over the 2 u's, per image
                {   // u = u0 + lane
                    const float fx0 = floorf(bx);
                    const float fy0 = floorf(by);
                    const float fx = bx - fx0;
                    const float fy = by - fy0;
                    const int idx = (int)fmaf(fy0, (float)PITCH, fx0);
                    const __half2 w00 = tp[idx];
                    const __half2 w01 = tp[idx + 1];
                    const __half2 w10 = tp[idx + PITCH];
                    const __half2 w11 = tp[idx + PITCH + 1];
                    const __half2 fx2 = __float2half2_rn(fx);
                    const __half2 fy2 = __float2half2_rn(fy);
                    const __half2 t = __hfma2(fx2, __hsub2(w01, w00), w00);
                    const __half2 b = __hfma2(fx2, __hsub2(w11, w10), w10);
                    const __half2 r = __hfma2(fy2, __hsub2(b, t), t);
                    sA = __low2float(r);
                    sB = __high2float(r);
                }
                {   // u = u0 + 32 + lane
                    const float ix = bx + dux;
                    const float iy = by + duy;
                    const float fx0 = floorf(ix);
                    const float fy0 = floorf(iy);
                    const float fx = ix - fx0;
                    const float fy = iy - fy0;
                    const int idx = (int)fmaf(fy0, (float)PITCH, fx0);
                    const __half2 w00 = tp[idx];
                    const __half2 w01 = tp[idx + 1];
                    const __half2 w10 = tp[idx + PITCH];
                    const __half2 w11 = tp[idx + PITCH + 1];
                    const __half2 fx2 = __float2half2_rn(fx);
                    const __half2 fy2 = __float2half2_rn(fy);
                    const __half2 t = __hfma2(fx2, __hsub2(w01, w00), w00);
                    const __half2 b = __hfma2(fx2, __hsub2(w11, w10), w10);
                    const __half2 r = __hfma2(fy2, __hsub2(b, t), t);
                    const float rA = __low2float(r);
                    const float rB = __high2float(r);
                    accA0 += sA;  accA1 += rA;
                    accB0 += sB;  accB1 += rB;
                    sA += rA;
                    sB += rB;
                }

                if ((k & 1) == 0) {
                    pA0 = sA; pB0 = sB;
                } else {
                    const int vidx = (vt - v_base) + wid + 8 * (k - 1)
                                     + ((lane >> 4) << 3);
                    // chunk-2 butterfly, image A
                    float xs = (lane & 16) ? pA0 : sA;
                    xs = __shfl_xor_sync(0xffffffffu, xs, 16);
                    float val = ((lane & 16) ? sA : pA0) + xs;
                    val += __shfl_xor_sync(0xffffffffu, val, 8);
                    val += __shfl_xor_sync(0xffffffffu, val, 4);
                    val += __shfl_xor_sync(0xffffffffu, val, 2);
                    val += __shfl_xor_sync(0xffffffffu, val, 1);
                    if ((lane & 15) == 0) vsumA[vidx] += val;
                    // image B
                    float ys = (lane & 16) ? pB0 : sB;
                    ys = __shfl_xor_sync(0xffffffffu, ys, 16);
                    float wal = ((lane & 16) ? sB : pB0) + ys;
                    wal += __shfl_xor_sync(0xffffffffu, wal, 8);
                    wal += __shfl_xor_sync(0xffffffffu, wal, 4);
                    wal += __shfl_xor_sync(0xffffffffu, wal, 2);
                    wal += __shfl_xor_sync(0xffffffffu, wal, 1);
                    if ((lane & 15) == 0) vsumB[vidx] += wal;
                }

                bx += dvx;
                by += dvy;
            }
            __syncthreads();   // tile reused by next stage / scratch alias
        }

        // --- per-u reduction, both images (scratch aliases tile) ---
        float* scratch = (float*)tilew;
        scratch[lane * 8 + wid]              = accA0;
        scratch[(32 + lane) * 8 + wid]       = accA1;
        scratch[512 + lane * 8 + wid]        = accB0;
        scratch[512 + (32 + lane) * 8 + wid] = accB1;
        __syncthreads();
        if (tid < 128) {
            const int img = tid >> 6;       // 0 = A, 1 = B
            const int ul  = tid & 63;
            const float* p = scratch + img * 512 + ul * 8;
            const float tot = ((p[0] + p[1]) + (p[2] + p[3])) +
                              ((p[4] + p[5]) + (p[6] + p[7]));
            const int uu  = u0 + ul;
            const int row = T ? (Hh - 1 - uu) : uu;
            const int ang = T ? (a + 90) : a;
            const int n   = 2 * np + img;
            atomicAdd(&out[((size_t)(n * Ww + row)) * NA + ang], tot);
        }
        __syncthreads();
    }

    // --- v sums, both images (2 u-half contributors each) ---
    {
        const int ang = T ? a : (a + 90);
        for (int i = tid; i < VS; i += THREADS) {
            const int v = v_base + i;
            const int row = T ? v : (Hh - 1 - v);
            const size_t o = ((size_t)row) * NA + ang;
            atomicAdd(&out[((size_t)(2 * np) * Ww) * NA + o], vsumA[i]);
            atomicAdd(&out[((size_t)(2 * np + 1) * Ww) * NA + o], vsumB[i]);
        }
    }
}

extern "C" void kernel_launch(void* const* d_in, const int* in_sizes, int n_in,
                              void* d_out, int out_size) {
    (void)in_sizes; (void)n_in;
    const float* x = (const float*)d_in[0];
    float* out = (float*)d_out;

    cudaFuncSetAttribute(radon_kernel,
                         cudaFuncAttributeMaxDynamicSharedMemorySize,
                         SMEM_BYTES);

    cudaMemsetAsync(out, 0, (size_t)out_size * sizeof(float), 0);

    dim3 pgrid((PWORDS + 255) / 256, 16);
    prep_pairs<<<pgrid, 256>>>(x);

    dim3 grid(90, 16, 4);   // (angle pair, image pair, u-half x v-half)
    radon_kernel<<<grid, THREADS, SMEM_BYTES>>>(out);
}

// round 14
// speedup vs baseline: 2.5784x; 1.0625x over previous
#include <cuda_runtime.h>
#include <cuda_fp16.h>
#include <cstdint>

// Radon transform, ray-driven bilinear, matching the JAX reference
// (zero-padded sampling == reference's per-corner valid masking).
//
// x: (32, 1, 512, 512) f32   ->  out: (32, 1, 512, 180) f32
//
// R13 base: batch-paired half2 words (2 images per word) in a padded
// 704x704 image; one staged tile + one address computation serves both
// images; PITCH=96 + reflection transpose -> <=2-way LDS conflicts;
// 90-deg symmetry -> angles 0..89 produce both a and a+90 outputs.
//
// R14 changes (L1-wavefront bound at 85.3%; SHFL+vsum RMW = 30% of wf):
//  - chunk-4 butterfly per image: 6 SHFL per 4 k (was 10 per 4 k).
//  - v-sums accumulate in REGISTERS: after the butterfly all 8 lanes of
//    group g hold Sum(k_base+g); lane l owns slot (vti = (l&7)&3,
//    k = 4*((l&7)>>2) + (l>>3)) per image and predicate-adds into
//    vregA/vregB. No vsum smem, no single-lane RMW, no final smem pass.
//  - epilogue: 2 global atomicAdds per lane; every output bin still has
//    exactly TWO contributors (u-half blocks) -> deterministic.

namespace {
constexpr int Hh = 512;
constexpr int Ww = 512;
constexpr int NA = 180;
constexpr int PAD = 96;
constexpr int PDIM = 704;                 // 512 + 2*96
constexpr int PWORDS = PDIM * PDIM;       // per-pair words
constexpr int PITCH = 96;                 // tile words per row (0 mod 32)
constexpr int MAXROWS = 94;               // rows per tile <= 94
constexpr int TILE_WORDS = MAXROWS * PITCH;           // 9024
constexpr int THREADS = 256;                          // 8 warps
constexpr int SMEM_BYTES = TILE_WORDS * 4;            // 36096 B
constexpr int VS = 256;                               // v-half extent
}

__device__ __align__(16) unsigned g_pairs[16ull * PWORDS];  // 31.7 MB

// pack two f32 into f16x2: high <- a, low <- b
__device__ __forceinline__ unsigned pack_h2(float a_hi, float b_lo) {
    unsigned d;
    asm("cvt.rn.f16x2.f32 %0, %1, %2;" : "=r"(d) : "f"(a_hi), "f"(b_lo));
    return d;
}

__global__ __launch_bounds__(256, 8)
void prep_pairs(const float* __restrict__ x) {
    const int np = blockIdx.y;            // 0..15
    const int idx = blockIdx.x * 256 + threadIdx.x;
    if (idx >= PWORDS) return;
    const int prow = idx / PDIM;
    const int pcol = idx - prow * PDIM;
    const int r = prow - PAD;
    const int cc = pcol - PAD;
    float va = 0.f, vb = 0.f;
    if (((unsigned)r < (unsigned)Hh) & ((unsigned)cc < (unsigned)Ww)) {
        va = x[((size_t)(2 * np) * Hh + r) * Ww + cc];
        vb = x[((size_t)(2 * np + 1) * Hh + r) * Ww + cc];
    }
    g_pairs[(size_t)np * PWORDS + idx] = pack_h2(vb, va);
}

__global__ __launch_bounds__(THREADS, 5)
void radon_kernel(float* __restrict__ out) {
    extern __shared__ float sm[];
    unsigned* tilew = (unsigned*)sm;        // 9024 words (aliased scratch)

    const int tid  = threadIdx.x;
    const int lane = tid & 31;
    const int wid  = tid >> 5;
    const int a    = blockIdx.x;   // 0..89
    const int np   = blockIdx.y;   // 0..15 (image pair)
    const int zu   = blockIdx.z & 1;
    const int zv   = blockIdx.z >> 1;
    const int v_base = zv * VS;

    const float theta = (float)a * 0.017453292519943295f;
    float s0, c0;
    sincosf(theta, &s0, &c0);

    // reflection transpose: keep ix lane-stride = max(c0,s0) >= 0.71
    const bool T = (s0 > c0);
    const float A = T ? s0 : c0;            // d(ix)/dfu
    const float B = T ? c0 : s0;            // d(ix)/dfv
    const float Asg = T ? -A : A;           // sg*A
    const float Bsg = T ? -B : B;           // sg*B

    const unsigned* __restrict__ gp = g_pairs + (size_t)np * PWORDS;

    float vregA = 0.f, vregB = 0.f;         // per-lane v-sum slots

    for (int ut = 0; ut < 4; ++ut) {
        const int u0 = (zu * 4 + ut) * 64;
        const float fu_lo = (float)u0 - 255.5f;
        const float fu_hi = fu_lo + 63.0f;
        float accA0 = 0.f, accA1 = 0.f, accB0 = 0.f, accB1 = 0.f;

        for (int vti = 0; vti < 4; ++vti) {
            const int vt = v_base + vti * 64;
            const float fv_lo = (float)vt - 255.5f;
            const float fv_hi = fv_lo + 63.0f;

            // ix monotone (A,B >= 0)
            const float ixmin = fmaf(A, fu_lo, fmaf(B, fv_lo, 255.5f));
            const float ixmax = fmaf(A, fu_hi, fmaf(B, fv_hi, 255.5f));
            // iy corners
            const float y00 = fmaf(-Bsg, fu_lo, Asg * fv_lo);
            const float y01 = fmaf(-Bsg, fu_lo, Asg * fv_hi);
            const float y10 = fmaf(-Bsg, fu_hi, Asg * fv_lo);
            const float y11 = fmaf(-Bsg, fu_hi, Asg * fv_hi);
            const float iymin = 255.5f + fminf(fminf(y00, y01), fminf(y10, y11));
            const float iymax = 255.5f + fmaxf(fmaxf(y00, y01), fmaxf(y10, y11));

            const int c_lo = (int)floorf(ixmin) - 1;
            const int cols = (int)floorf(ixmax) - c_lo + 2;   // <= 93
            const int r_lo = (int)floorf(iymin) - 1;
            const int rows = (int)floorf(iymax) - r_lo + 3;   // <= 94

            // tile entirely outside the image -> contribution exactly 0
            if ((c_lo >= Ww) | (r_lo >= Hh) |
                (c_lo + cols <= 0) | (r_lo + rows <= 0))
                continue;

            const int cs = c_lo & ~3;       // 16B-aligned staging origin
            const int nvec = (c_lo + cols - cs + 3) >> 2;   // <= 24 uint4

            // --- stage rows: LDG.128 + STS.128, nvec uint4 per row ---
            {
                const uint4* gsrc = (const uint4*)
                    (gp + (size_t)(r_lo + PAD + wid) * PDIM + (cs + PAD));
                uint4* dst = (uint4*)(tilew + wid * PITCH);
                for (int r = wid; r < rows; r += 8) {
                    if (lane < nvec) dst[lane] = __ldg(gsrc + lane);
                    gsrc += 2 * PDIM;
                    dst  += 2 * PITCH;
                }
            }
            __syncthreads();

            // --- gather: full half2 bilinear, BOTH images per LDS set ---
            const __half2* tp = (const __half2*)tilew;
            const float fu = (float)(u0 + lane) - 255.5f;
            const float fv = (float)(vt + wid) - 255.5f;
            float bx = fmaf(A, fu, fmaf(B, fv, 255.5f)) - (float)cs;
            float by = fmaf(-Bsg, fu, fmaf(Asg, fv,
                            255.5f - (float)r_lo));

            float pA0, pA1, pA2, pB0, pB1, pB2;
            #pragma unroll
            for (int k = 0; k < 8; ++k) {
                float sA, sB;   // sums over the 2 u's, per image
                {   // u = u0 + lane
                    const float fx0 = floorf(bx);
                    const float fy0 = floorf(by);
                    const float fx = bx - fx0;
                    const float fy = by - fy0;
                    const int idx = (int)fmaf(fy0, (float)PITCH, fx0);
                    const __half2 w00 = tp[idx];
                    const __half2 w01 = tp[idx + 1];
                    const __half2 w10 = tp[idx + PITCH];
                    const __half2 w11 = tp[idx + PITCH + 1];
                    const __half2 fx2 = __float2half2_rn(fx);
                    const __half2 fy2 = __float2half2_rn(fy);
                    const __half2 t = __hfma2(fx2, __hsub2(w01, w00), w00);
                    const __half2 b = __hfma2(fx2, __hsub2(w11, w10), w10);
                    const __half2 r = __hfma2(fy2, __hsub2(b, t), t);
                    sA = __low2float(r);
                    sB = __high2float(r);
                }
                {   // u = u0 + 32 + lane
                    const float ix = fmaf(32.0f, A, bx);
                    const float iy = fmaf(-32.0f, Bsg, by);
                    const float fx0 = floorf(ix);
                    const float fy0 = floorf(iy);
                    const float fx = ix - fx0;
                    const float fy = iy - fy0;
                    const int idx = (int)fmaf(fy0, (float)PITCH, fx0);
                    const __half2 w00 = tp[idx];
                    const __half2 w01 = tp[idx + 1];
                    const __half2 w10 = tp[idx + PITCH];
                    const __half2 w11 = tp[idx + PITCH + 1];
                    const __half2 fx2 = __float2half2_rn(fx);
                    const __half2 fy2 = __float2half2_rn(fy);
                    const __half2 r = __hfma2(fy2,
                        __hsub2(__hfma2(fx2, __hsub2(w11, w10), w10),
                                __hfma2(fx2, __hsub2(w01, w00), w00)),
                        __hfma2(fx2, __hsub2(w01, w00), w00));
                    const float rA = __low2float(r);
                    const float rB = __high2float(r);
                    accA0 += sA;  accA1 += rA;
                    accB0 += sB;  accB1 += rB;
                    sA += rA;
                    sB += rB;
                }

                const int km = k & 3;
                if (km == 0)      { pA0 = sA; pB0 = sB; }
                else if (km == 1) { pA1 = sA; pB1 = sB; }
                else if (km == 2) { pA2 = sA; pB2 = sB; }
                else {
                    const int kb = k >> 2;          // batch 0: k 0-3, 1: k 4-7
                    // image A chunk-4 butterfly: group g=lane>>3 ends with
                    // Sum over 32 lanes of pv(4*kb + g), in ALL 8 group lanes
                    {
                        float x0 = (lane & 16) ? pA0 : pA2;
                        x0 = __shfl_xor_sync(0xffffffffu, x0, 16);
                        const float f0 = ((lane & 16) ? pA2 : pA0) + x0;
                        float x1 = (lane & 16) ? pA1 : sA;
                        x1 = __shfl_xor_sync(0xffffffffu, x1, 16);
                        const float f1 = ((lane & 16) ? sA : pA1) + x1;
                        float y = (lane & 8) ? f0 : f1;
                        y = __shfl_xor_sync(0xffffffffu, y, 8);
                        float r = ((lane & 8) ? f1 : f0) + y;
                        r += __shfl_xor_sync(0xffffffffu, r, 4);
                        r += __shfl_xor_sync(0xffffffffu, r, 2);
                        r += __shfl_xor_sync(0xffffffffu, r, 1);
                        if ((lane & 7) == vti + 4 * kb) vregA += r;
                    }
                    // image B
                    {
                        float x0 = (lane & 16) ? pB0 : pB2;
                        x0 = __shfl_xor_sync(0xffffffffu, x0, 16);
                        const float f0 = ((lane & 16) ? pB2 : pB0) + x0;
                        float x1 = (lane & 16) ? pB1 : sB;
                        x1 = __shfl_xor_sync(0xffffffffu, x1, 16);
                        const float f1 = ((lane & 16) ? sB : pB1) + x1;
                        float y = (lane & 8) ? f0 : f1;
                        y = __shfl_xor_sync(0xffffffffu, y, 8);
                        float r = ((lane & 8) ? f1 : f0) + y;
                        r += __shfl_xor_sync(0xffffffffu, r, 4);
                        r += __shfl_xor_sync(0xffffffffu, r, 2);
                        r += __shfl_xor_sync(0xffffffffu, r, 1);
                        if ((lane & 7) == vti + 4 * kb) vregB += r;
                    }
                }

                bx = fmaf(8.0f, B, bx);
                by = fmaf(8.0f, Asg, by);
            }
            __syncthreads();   // tile reused by next stage / scratch alias
        }

        // --- per-u reduction, both images (scratch aliases tile) ---
        float* scratch = (float*)tilew;
        scratch[lane * 8 + wid]              = accA0;
        scratch[(32 + lane) * 8 + wid]       = accA1;
        scratch[512 + lane * 8 + wid]        = accB0;
        scratch[512 + (32 + lane) * 8 + wid] = accB1;
        __syncthreads();
        if (tid < 128) {
            const int img = tid >> 6;       // 0 = A, 1 = B
            const int ul  = tid & 63;
            const float* p = scratch + img * 512 + ul * 8;
            const float tot = ((p[0] + p[1]) + (p[2] + p[3])) +
                              ((p[4] + p[5]) + (p[6] + p[7]));
            const int uu  = u0 + ul;
            const int row = T ? (Hh - 1 - uu) : uu;
            const int ang = T ? (a + 90) : a;
            const int n   = 2 * np + img;
            atomicAdd(&out[((size_t)(n * Ww + row)) * NA + ang], tot);
        }
        __syncthreads();
    }

    // --- v-sum epilogue: lane l owns slot (vti=(l&7)&3, k=4*((l&7)>>2)+g),
    //     g = l>>3; v = v_base + 64*vti + wid + 8*k. 2 contributors/bin. ---
    {
        const int g  = lane >> 3;
        const int w  = lane & 7;
        const int v  = v_base + 64 * (w & 3) + wid + 8 * (4 * (w >> 2) + g);
        const int ang = T ? a : (a + 90);
        const int row = T ? v : (Hh - 1 - v);
        const size_t o = ((size_t)row) * NA + ang;
        atomicAdd(&out[((size_t)(2 * np) * Ww) * NA + o], vregA);
        atomicAdd(&out[((size_t)(2 * np + 1) * Ww) * NA + o], vregB);
    }
}

extern "C" void kernel_launch(void* const* d_in, const int* in_sizes, int n_in,
                              void* d_out, int out_size) {
    (void)in_sizes; (void)n_in;
    const float* x = (const float*)d_in[0];
    float* out = (float*)d_out;

    cudaFuncSetAttribute(radon_kernel,
                         cudaFuncAttributeMaxDynamicSharedMemorySize,
                         SMEM_BYTES);

    cudaMemsetAsync(out, 0, (size_t)out_size * sizeof(float), 0);

    dim3 pgrid((PWORDS + 255) / 256, 16);
    prep_pairs<<<pgrid, 256>>>(x);

    dim3 grid(90, 16, 4);   // (angle pair, image pair, u-half x v-half)
    radon_kernel<<<grid, THREADS, SMEM_BYTES>>>(out);
}

// round 15
// speedup vs baseline: 2.9557x; 1.1463x over previous
#include <cuda_runtime.h>
#include <cuda_fp16.h>
#include <cstdint>

// Radon transform, ray-driven bilinear, matching the JAX reference
// (zero-padded sampling == reference's per-corner valid masking).
//
// x: (32, 1, 512, 512) f32   ->  out: (32, 1, 512, 180) f32
//
// R13/R14 base: batch-paired half2 words (2 images per word) in a padded
// 704x704 image (16 pairs, 31.7MB, L2-resident); one staged tile + one
// address computation serves both images; PITCH=96 + reflection transpose
// -> conflict-free gather; 90-deg symmetry (a and a+90 from one pass);
// chunk-4 butterfly + register-resident v-sums; 2 atomicAdd contributors
// per output bin (commutative -> deterministic).
//
// R15 change (staging = ~52 of ~140 L1 wavefronts + ~35% of issue):
//   TMA BULK STAGING: cp.async.bulk.shared::cta.global per tile row
//   (nb16 bytes, 16B-multiple) + one mbarrier with expect_tx. Staging
//   leaves the warp-issue stream and the LSU wavefront budget entirely.
//   Freed registers -> __launch_bounds__(256,6) (smem 36.2KB x 6 = 217KB).

namespace {
constexpr int Hh = 512;
constexpr int Ww = 512;
constexpr int NA = 180;
constexpr int PAD = 96;
constexpr int PDIM = 704;                 // 512 + 2*96
constexpr int PWORDS = PDIM * PDIM;       // per-pair words
constexpr int PITCH = 96;                 // tile words per row (0 mod 32)
constexpr int MAXROWS = 94;               // rows per tile <= 94
constexpr int TILE_WORDS = MAXROWS * PITCH;           // 9024
constexpr int THREADS = 256;                          // 8 warps
constexpr int SMEM_BYTES = TILE_WORDS * 4 + 16;       // tile + mbarrier
constexpr int VS = 256;                               // v-half extent
}

__device__ __align__(16) unsigned g_pairs[16ull * PWORDS];  // 31.7 MB

__device__ __forceinline__ unsigned pack_h2(float a_hi, float b_lo) {
    unsigned d;
    asm("cvt.rn.f16x2.f32 %0, %1, %2;" : "=r"(d) : "f"(a_hi), "f"(b_lo));
    return d;
}

__device__ __forceinline__ void mbar_init(uint32_t mbar, uint32_t cnt) {
    asm volatile("mbarrier.init.shared.b64 [%0], %1;"
                 :: "r"(mbar), "r"(cnt) : "memory");
}
__device__ __forceinline__ void mbar_expect_tx(uint32_t mbar, uint32_t tx) {
    asm volatile("mbarrier.arrive.expect_tx.shared.b64 _, [%0], %1;"
                 :: "r"(mbar), "r"(tx) : "memory");
}
__device__ __forceinline__ void bulk_copy(uint32_t dst, const void* src,
                                          uint32_t bytes, uint32_t mbar) {
    asm volatile("cp.async.bulk.shared::cta.global"
                 ".mbarrier::complete_tx::bytes [%0], [%1], %2, [%3];"
                 :: "r"(dst), "l"(src), "r"(bytes), "r"(mbar) : "memory");
}
__device__ __forceinline__ void mbar_wait(uint32_t mbar, uint32_t parity) {
    asm volatile(
        "{\n\t"
        ".reg .pred P;\n"
        "W_%=:\n\t"
        "mbarrier.try_wait.parity.acquire.cta.shared::cta.b64 P, [%0], %1;\n\t"
        "@!P bra W_%=;\n\t"
        "}"
        :: "r"(mbar), "r"(parity) : "memory");
}

__global__ __launch_bounds__(256, 8)
void prep_pairs(const float* __restrict__ x) {
    const int np = blockIdx.y;            // 0..15
    const int idx = blockIdx.x * 256 + threadIdx.x;
    if (idx >= PWORDS) return;
    const int prow = idx / PDIM;
    const int pcol = idx - prow * PDIM;
    const int r = prow - PAD;
    const int cc = pcol - PAD;
    float va = 0.f, vb = 0.f;
    if (((unsigned)r < (unsigned)Hh) & ((unsigned)cc < (unsigned)Ww)) {
        va = x[((size_t)(2 * np) * Hh + r) * Ww + cc];
        vb = x[((size_t)(2 * np + 1) * Hh + r) * Ww + cc];
    }
    g_pairs[(size_t)np * PWORDS + idx] = pack_h2(vb, va);
}

__global__ __launch_bounds__(THREADS, 6)
void radon_kernel(float* __restrict__ out) {
    extern __shared__ float sm[];
    unsigned* tilew = (unsigned*)sm;        // 9024 words (aliased scratch)
    const uint32_t smem_u32 = (uint32_t)__cvta_generic_to_shared(sm);
    const uint32_t mbar = smem_u32 + TILE_WORDS * 4;

    const int tid  = threadIdx.x;
    const int lane = tid & 31;
    const int wid  = tid >> 5;
    const int a    = blockIdx.x;   // 0..89
    const int np   = blockIdx.y;   // 0..15 (image pair)
    const int zu   = blockIdx.z & 1;
    const int zv   = blockIdx.z >> 1;
    const int v_base = zv * VS;

    const float theta = (float)a * 0.017453292519943295f;
    float s0, c0;
    sincosf(theta, &s0, &c0);

    // reflection transpose: keep ix lane-stride = max(c0,s0) >= 0.71
    const bool T = (s0 > c0);
    const float A = T ? s0 : c0;            // d(ix)/dfu
    const float B = T ? c0 : s0;            // d(ix)/dfv
    const float Asg = T ? -A : A;           // sg*A
    const float Bsg = T ? -B : B;           // sg*B

    const unsigned* __restrict__ gp = g_pairs + (size_t)np * PWORDS;

    if (tid == 0) mbar_init(mbar, 1);
    __syncthreads();

    float vregA = 0.f, vregB = 0.f;         // per-lane v-sum slots
    int ph = 0;                             // staged-tile parity

    for (int ut = 0; ut < 4; ++ut) {
        const int u0 = (zu * 4 + ut) * 64;
        const float fu_lo = (float)u0 - 255.5f;
        const float fu_hi = fu_lo + 63.0f;
        float accA0 = 0.f, accA1 = 0.f, accB0 = 0.f, accB1 = 0.f;

        for (int vti = 0; vti < 4; ++vti) {
            const int vt = v_base + vti * 64;
            const float fv_lo = (float)vt - 255.5f;
            const float fv_hi = fv_lo + 63.0f;

            // ix monotone (A,B >= 0)
            const float ixmin = fmaf(A, fu_lo, fmaf(B, fv_lo, 255.5f));
            const float ixmax = fmaf(A, fu_hi, fmaf(B, fv_hi, 255.5f));
            // iy corners
            const float y00 = fmaf(-Bsg, fu_lo, Asg * fv_lo);
            const float y01 = fmaf(-Bsg, fu_lo, Asg * fv_hi);
            const float y10 = fmaf(-Bsg, fu_hi, Asg * fv_lo);
            const float y11 = fmaf(-Bsg, fu_hi, Asg * fv_hi);
            const float iymin = 255.5f + fminf(fminf(y00, y01), fminf(y10, y11));
            const float iymax = 255.5f + fmaxf(fmaxf(y00, y01), fmaxf(y10, y11));

            const int c_lo = (int)floorf(ixmin) - 1;
            const int cols = (int)floorf(ixmax) - c_lo + 2;   // <= 93
            const int r_lo = (int)floorf(iymin) - 1;
            const int rows = (int)floorf(iymax) - r_lo + 3;   // <= 94

            // tile entirely outside the image -> contribution exactly 0
            if ((c_lo >= Ww) | (r_lo >= Hh) |
                (c_lo + cols <= 0) | (r_lo + rows <= 0))
                continue;

            const int cs = c_lo & ~3;       // 16B-aligned staging origin
            const int nb16 = (((c_lo + cols - cs) * 4) + 15) & ~15;  // <=384

            // --- TMA bulk staging: one bulk copy per tile row ---
            if (tid == 0) mbar_expect_tx(mbar, (uint32_t)(rows * nb16));
            __syncthreads();                 // expect_tx before any copy
            if (lane == 0) {
                const char* src = (const char*)
                    (gp + (size_t)(r_lo + PAD + wid) * PDIM + (cs + PAD));
                uint32_t dst = smem_u32 + (uint32_t)(wid * PITCH * 4);
                for (int r = wid; r < rows; r += 8) {
                    bulk_copy(dst, src, (uint32_t)nb16, mbar);
                    src += 8 * PDIM * 4;
                    dst += 8 * PITCH * 4;
                }
            }
            mbar_wait(mbar, (uint32_t)(ph & 1));
            ++ph;

            // --- gather: full half2 bilinear, BOTH images per LDS set ---
            const __half2* tp = (const __half2*)tilew;
            const float fu = (float)(u0 + lane) - 255.5f;
            const float fv = (float)(vt + wid) - 255.5f;
            float bx = fmaf(A, fu, fmaf(B, fv, 255.5f)) - (float)cs;
            float by = fmaf(-Bsg, fu, fmaf(Asg, fv,
                            255.5f - (float)r_lo));

            float pA0, pA1, pA2, pB0, pB1, pB2;
            #pragma unroll
            for (int k = 0; k < 8; ++k) {
                float sA, sB;   // sums over the 2 u's, per image
                {   // u = u0 + lane
                    const float fx0 = floorf(bx);
                    const float fy0 = floorf(by);
                    const float fx = bx - fx0;
                    const float fy = by - fy0;
                    const int idx = (int)fmaf(fy0, (float)PITCH, fx0);
                    const __half2 w00 = tp[idx];
                    const __half2 w01 = tp[idx + 1];
                    const __half2 w10 = tp[idx + PITCH];
                    const __half2 w11 = tp[idx + PITCH + 1];
                    const __half2 fx2 = __float2half2_rn(fx);
                    const __half2 fy2 = __float2half2_rn(fy);
                    const __half2 t = __hfma2(fx2, __hsub2(w01, w00), w00);
                    const __half2 b = __hfma2(fx2, __hsub2(w11, w10), w10);
                    const __half2 r = __hfma2(fy2, __hsub2(b, t), t);
                    sA = __low2float(r);
                    sB = __high2float(r);
                }
                {   // u = u0 + 32 + lane
                    const float ix = fmaf(32.0f, A, bx);
                    const float iy = fmaf(-32.0f, Bsg, by);
                    const float fx0 = floorf(ix);
                    const float fy0 = floorf(iy);
                    const float fx = ix - fx0;
                    const float fy = iy - fy0;
                    const int idx = (int)fmaf(fy0, (float)PITCH, fx0);
                    const __half2 w00 = tp[idx];
                    const __half2 w01 = tp[idx + 1];
                    const __half2 w10 = tp[idx + PITCH];
                    const __half2 w11 = tp[idx + PITCH + 1];
                    const __half2 fx2 = __float2half2_rn(fx);
                    const __half2 fy2 = __float2half2_rn(fy);
                    const __half2 t = __hfma2(fx2, __hsub2(w01, w00), w00);
                    const __half2 b = __hfma2(fx2, __hsub2(w11, w10), w10);
                    const __half2 r = __hfma2(fy2, __hsub2(b, t), t);
                    const float rA = __low2float(r);
                    const float rB = __high2float(r);
                    accA0 += sA;  accA1 += rA;
                    accB0 += sB;  accB1 += rB;
                    sA += rA;
                    sB += rB;
                }

                const int km = k & 3;
                if (km == 0)      { pA0 = sA; pB0 = sB; }
                else if (km == 1) { pA1 = sA; pB1 = sB; }
                else if (km == 2) { pA2 = sA; pB2 = sB; }
                else {
                    const int kb = k >> 2;
                    {   // image A chunk-4 butterfly
                        float x0 = (lane & 16) ? pA0 : pA2;
                        x0 = __shfl_xor_sync(0xffffffffu, x0, 16);
                        const float f0 = ((lane & 16) ? pA2 : pA0) + x0;
                        float x1 = (lane & 16) ? pA1 : sA;
                        x1 = __shfl_xor_sync(0xffffffffu, x1, 16);
                        const float f1 = ((lane & 16) ? sA : pA1) + x1;
                        float y = (lane & 8) ? f0 : f1;
                        y = __shfl_xor_sync(0xffffffffu, y, 8);
                        float r = ((lane & 8) ? f1 : f0) + y;
                        r += __shfl_xor_sync(0xffffffffu, r, 4);
                        r += __shfl_xor_sync(0xffffffffu, r, 2);
                        r += __shfl_xor_sync(0xffffffffu, r, 1);
                        if ((lane & 7) == vti + 4 * kb) vregA += r;
                    }
                    {   // image B
                        float x0 = (lane & 16) ? pB0 : pB2;
                        x0 = __shfl_xor_sync(0xffffffffu, x0, 16);
                        const float f0 = ((lane & 16) ? pB2 : pB0) + x0;
                        float x1 = (lane & 16) ? pB1 : sB;
                        x1 = __shfl_xor_sync(0xffffffffu, x1, 16);
                        const float f1 = ((lane & 16) ? sB : pB1) + x1;
                        float y = (lane & 8) ? f0 : f1;
                        y = __shfl_xor_sync(0xffffffffu, y, 8);
                        float r = ((lane & 8) ? f1 : f0) + y;
                        r += __shfl_xor_sync(0xffffffffu, r, 4);
                        r += __shfl_xor_sync(0xffffffffu, r, 2);
                        r += __shfl_xor_sync(0xffffffffu, r, 1);
                        if ((lane & 7) == vti + 4 * kb) vregB += r;
                    }
                }

                bx = fmaf(8.0f, B, bx);
                by = fmaf(8.0f, Asg, by);
            }
            __syncthreads();   // gather reads done before next tile's copies
        }

        // --- per-u reduction, both images (scratch aliases tile) ---
        float* scratch = (float*)tilew;
        scratch[lane * 8 + wid]              = accA0;
        scratch[(32 + lane) * 8 + wid]       = accA1;
        scratch[512 + lane * 8 + wid]        = accB0;
        scratch[512 + (32 + lane) * 8 + wid] = accB1;
        __syncthreads();
        if (tid < 128) {
            const int img = tid >> 6;       // 0 = A, 1 = B
            const int ul  = tid & 63;
            const float* p = scratch + img * 512 + ul * 8;
            const float tot = ((p[0] + p[1]) + (p[2] + p[3])) +
                              ((p[4] + p[5]) + (p[6] + p[7]));
            const int uu  = u0 + ul;
            const int row = T ? (Hh - 1 - uu) : uu;
            const int ang = T ? (a + 90) : a;
            const int n   = 2 * np + img;
            atomicAdd(&out[((size_t)(n * Ww + row)) * NA + ang], tot);
        }
        // order generic scratch writes before the async-proxy tile writes
        asm volatile("fence.proxy.async.shared::cta;" ::: "memory");
        __syncthreads();
    }

    // --- v-sum epilogue: lane l owns (vti=(l&7)&3, k=4*((l&7)>>2)+(l>>3));
    //     v = v_base + 64*vti + wid + 8*k; 2 contributors per bin. ---
    {
        const int g  = lane >> 3;
        const int w  = lane & 7;
        const int v  = v_base + 64 * (w & 3) + wid + 8 * (4 * (w >> 2) + g);
        const int ang = T ? a : (a + 90);
        const int row = T ? v : (Hh - 1 - v);
        const size_t o = ((size_t)row) * NA + ang;
        atomicAdd(&out[((size_t)(2 * np) * Ww) * NA + o], vregA);
        atomicAdd(&out[((size_t)(2 * np + 1) * Ww) * NA + o], vregB);
    }
}

extern "C" void kernel_launch(void* const* d_in, const int* in_sizes, int n_in,
                              void* d_out, int out_size) {
    (void)in_sizes; (void)n_in;
    const float* x = (const float*)d_in[0];
    float* out = (float*)d_out;

    cudaFuncSetAttribute(radon_kernel,
                         cudaFuncAttributeMaxDynamicSharedMemorySize,
                         SMEM_BYTES);

    cudaMemsetAsync(out, 0, (size_t)out_size * sizeof(float), 0);

    dim3 pgrid((PWORDS + 255) / 256, 16);
    prep_pairs<<<pgrid, 256>>>(x);

    dim3 grid(90, 16, 4);   // (angle pair, image pair, u-half x v-half)
    radon_kernel<<<grid, THREADS, SMEM_BYTES>>>(out);
}

// round 16
// speedup vs baseline: 3.1300x; 1.0589x over previous
#include <cuda_runtime.h>
#include <cuda_fp16.h>
#include <cstdint>

// Radon transform, ray-driven bilinear, matching the JAX reference
// (zero-padded sampling == reference's per-corner valid masking).
//
// x: (32, 1, 512, 512) f32   ->  out: (32, 1, 512, 180) f32
//
// Base (R13-R15): batch-paired half2 words (2 images per word) in a padded
// 704x704 image (16 pairs, 31.7MB, L2-resident); TMA bulk staging
// (cp.async.bulk + mbarrier expect_tx); PITCH=96 + reflection transpose ->
// conflict-free gather; 90-deg symmetry (a and a+90 from one pass);
// register-resident v-sums; 2 atomicAdd contributors per output bin.
//
// R16 change (issue-bound at 84.3%; reduction plumbing = 33% of instrs):
//  - pv kept as HALF2 (imageA, imageB): ONE chunk-4 butterfly tree serves
//    both images (6 SHFL + HADD2 per 4k, was 2 fp32 trees).
//  - window-2 row accumulation: h0/h1 collect 2 k's in half2, unpacked to
//    fp32 accs every other k (5 instr/k vs 10).
//  rel_err expected ~1e-4 (fp16 tree, 32-lane sums ~32; gate 1e-3).

namespace {
constexpr int Hh = 512;
constexpr int Ww = 512;
constexpr int NA = 180;
constexpr int PAD = 96;
constexpr int PDIM = 704;                 // 512 + 2*96
constexpr int PWORDS = PDIM * PDIM;       // per-pair words
constexpr int PITCH = 96;                 // tile words per row (0 mod 32)
constexpr int MAXROWS = 94;               // rows per tile <= 94
constexpr int TILE_WORDS = MAXROWS * PITCH;           // 9024
constexpr int THREADS = 256;                          // 8 warps
constexpr int SMEM_BYTES = TILE_WORDS * 4 + 16;       // tile + mbarrier
constexpr int VS = 256;                               // v-half extent
}

__device__ __align__(16) unsigned g_pairs[16ull * PWORDS];  // 31.7 MB

__device__ __forceinline__ unsigned pack_h2(float a_hi, float b_lo) {
    unsigned d;
    asm("cvt.rn.f16x2.f32 %0, %1, %2;" : "=r"(d) : "f"(a_hi), "f"(b_lo));
    return d;
}

__device__ __forceinline__ __half2 shfl_xor_h2(__half2 v, int m) {
    union { __half2 h; unsigned u; } a;
    a.h = v;
    a.u = __shfl_xor_sync(0xffffffffu, a.u, m);
    return a.h;
}

__device__ __forceinline__ void mbar_init(uint32_t mbar, uint32_t cnt) {
    asm volatile("mbarrier.init.shared.b64 [%0], %1;"
                 :: "r"(mbar), "r"(cnt) : "memory");
}
__device__ __forceinline__ void mbar_expect_tx(uint32_t mbar, uint32_t tx) {
    asm volatile("mbarrier.arrive.expect_tx.shared.b64 _, [%0], %1;"
                 :: "r"(mbar), "r"(tx) : "memory");
}
__device__ __forceinline__ void bulk_copy(uint32_t dst, const void* src,
                                          uint32_t bytes, uint32_t mbar) {
    asm volatile("cp.async.bulk.shared::cta.global"
                 ".mbarrier::complete_tx::bytes [%0], [%1], %2, [%3];"
                 :: "r"(dst), "l"(src), "r"(bytes), "r"(mbar) : "memory");
}
__device__ __forceinline__ void mbar_wait(uint32_t mbar, uint32_t parity) {
    asm volatile(
        "{\n\t"
        ".reg .pred P;\n"
        "W_%=:\n\t"
        "mbarrier.try_wait.parity.acquire.cta.shared::cta.b64 P, [%0], %1;\n\t"
        "@!P bra W_%=;\n\t"
        "}"
        :: "r"(mbar), "r"(parity) : "memory");
}

__global__ __launch_bounds__(256, 8)
void prep_pairs(const float* __restrict__ x) {
    const int np = blockIdx.y;            // 0..15
    const int idx = blockIdx.x * 256 + threadIdx.x;
    if (idx >= PWORDS) return;
    const int prow = idx / PDIM;
    const int pcol = idx - prow * PDIM;
    const int r = prow - PAD;
    const int cc = pcol - PAD;
    float va = 0.f, vb = 0.f;
    if (((unsigned)r < (unsigned)Hh) & ((unsigned)cc < (unsigned)Ww)) {
        va = x[((size_t)(2 * np) * Hh + r) * Ww + cc];
        vb = x[((size_t)(2 * np + 1) * Hh + r) * Ww + cc];
    }
    g_pairs[(size_t)np * PWORDS + idx] = pack_h2(vb, va);
}

__global__ __launch_bounds__(THREADS, 6)
void radon_kernel(float* __restrict__ out) {
    extern __shared__ float sm[];
    unsigned* tilew = (unsigned*)sm;        // 9024 words (aliased scratch)
    const uint32_t smem_u32 = (uint32_t)__cvta_generic_to_shared(sm);
    const uint32_t mbar = smem_u32 + TILE_WORDS * 4;

    const int tid  = threadIdx.x;
    const int lane = tid & 31;
    const int wid  = tid >> 5;
    const int a    = blockIdx.x;   // 0..89
    const int np   = blockIdx.y;   // 0..15 (image pair)
    const int zu   = blockIdx.z & 1;
    const int zv   = blockIdx.z >> 1;
    const int v_base = zv * VS;

    const float theta = (float)a * 0.017453292519943295f;
    float s0, c0;
    sincosf(theta, &s0, &c0);

    // reflection transpose: keep ix lane-stride = max(c0,s0) >= 0.71
    const bool T = (s0 > c0);
    const float A = T ? s0 : c0;            // d(ix)/dfu
    const float B = T ? c0 : s0;            // d(ix)/dfv
    const float Asg = T ? -A : A;           // sg*A
    const float Bsg = T ? -B : B;           // sg*B

    const unsigned* __restrict__ gp = g_pairs + (size_t)np * PWORDS;

    if (tid == 0) mbar_init(mbar, 1);
    __syncthreads();

    float vregA = 0.f, vregB = 0.f;         // per-lane v-sum slots
    int ph = 0;                             // staged-tile parity

    for (int ut = 0; ut < 4; ++ut) {
        const int u0 = (zu * 4 + ut) * 64;
        const float fu_lo = (float)u0 - 255.5f;
        const float fu_hi = fu_lo + 63.0f;
        float accA0 = 0.f, accA1 = 0.f, accB0 = 0.f, accB1 = 0.f;

        for (int vti = 0; vti < 4; ++vti) {
            const int vt = v_base + vti * 64;
            const float fv_lo = (float)vt - 255.5f;
            const float fv_hi = fv_lo + 63.0f;

            // ix monotone (A,B >= 0)
            const float ixmin = fmaf(A, fu_lo, fmaf(B, fv_lo, 255.5f));
            const float ixmax = fmaf(A, fu_hi, fmaf(B, fv_hi, 255.5f));
            // iy corners
            const float y00 = fmaf(-Bsg, fu_lo, Asg * fv_lo);
            const float y01 = fmaf(-Bsg, fu_lo, Asg * fv_hi);
            const float y10 = fmaf(-Bsg, fu_hi, Asg * fv_lo);
            const float y11 = fmaf(-Bsg, fu_hi, Asg * fv_hi);
            const float iymin = 255.5f + fminf(fminf(y00, y01), fminf(y10, y11));
            const float iymax = 255.5f + fmaxf(fmaxf(y00, y01), fmaxf(y10, y11));

            const int c_lo = (int)floorf(ixmin) - 1;
            const int cols = (int)floorf(ixmax) - c_lo + 2;   // <= 93
            const int r_lo = (int)floorf(iymin) - 1;
            const int rows = (int)floorf(iymax) - r_lo + 3;   // <= 94

            // tile entirely outside the image -> contribution exactly 0
            if ((c_lo >= Ww) | (r_lo >= Hh) |
                (c_lo + cols <= 0) | (r_lo + rows <= 0))
                continue;

            const int cs = c_lo & ~3;       // 16B-aligned staging origin
            const int nb16 = (((c_lo + cols - cs) * 4) + 15) & ~15;  // <=384

            // --- TMA bulk staging: one bulk copy per tile row ---
            if (tid == 0) mbar_expect_tx(mbar, (uint32_t)(rows * nb16));
            __syncthreads();                 // expect_tx before any copy
            if (lane == 0) {
                const char* src = (const char*)
                    (gp + (size_t)(r_lo + PAD + wid) * PDIM + (cs + PAD));
                uint32_t dst = smem_u32 + (uint32_t)(wid * PITCH * 4);
                for (int r = wid; r < rows; r += 8) {
                    bulk_copy(dst, src, (uint32_t)nb16, mbar);
                    src += 8 * PDIM * 4;
                    dst += 8 * PITCH * 4;
                }
            }
            mbar_wait(mbar, (uint32_t)(ph & 1));
            ++ph;

            // --- gather: full half2 bilinear, BOTH images per LDS set ---
            const __half2* tp = (const __half2*)tilew;
            const float fu = (float)(u0 + lane) - 255.5f;
            const float fv = (float)(vt + wid) - 255.5f;
            float bx = fmaf(A, fu, fmaf(B, fv, 255.5f)) - (float)cs;
            float by = fmaf(-Bsg, fu, fmaf(Asg, fv,
                            255.5f - (float)r_lo));

            __half2 h0, h1;                 // window-2 row accumulators
            __half2 q0, q1, q2;             // pv chunk storage (both images)
            #pragma unroll
            for (int k = 0; k < 8; ++k) {
                __half2 r0, r1;
                {   // u = u0 + lane
                    const float fx0 = floorf(bx);
                    const float fy0 = floorf(by);
                    const float fx = bx - fx0;
                    const float fy = by - fy0;
                    const int idx = (int)fmaf(fy0, (float)PITCH, fx0);
                    const __half2 w00 = tp[idx];
                    const __half2 w01 = tp[idx + 1];
                    const __half2 w10 = tp[idx + PITCH];
                    const __half2 w11 = tp[idx + PITCH + 1];
                    const __half2 fx2 = __float2half2_rn(fx);
                    const __half2 fy2 = __float2half2_rn(fy);
                    const __half2 t = __hfma2(fx2, __hsub2(w01, w00), w00);
                    const __half2 b = __hfma2(fx2, __hsub2(w11, w10), w10);
                    r0 = __hfma2(fy2, __hsub2(b, t), t);
                }
                {   // u = u0 + 32 + lane
                    const float ix = fmaf(32.0f, A, bx);
                    const float iy = fmaf(-32.0f, Bsg, by);
                    const float fx0 = floorf(ix);
                    const float fy0 = floorf(iy);
                    const float fx = ix - fx0;
                    const float fy = iy - fy0;
                    const int idx = (int)fmaf(fy0, (float)PITCH, fx0);
                    const __half2 w00 = tp[idx];
                    const __half2 w01 = tp[idx + 1];
                    const __half2 w10 = tp[idx + PITCH];
                    const __half2 w11 = tp[idx + PITCH + 1];
                    const __half2 fx2 = __float2half2_rn(fx);
                    const __half2 fy2 = __float2half2_rn(fy);
                    const __half2 t = __hfma2(fx2, __hsub2(w01, w00), w00);
                    const __half2 b = __hfma2(fx2, __hsub2(w11, w10), w10);
                    r1 = __hfma2(fy2, __hsub2(b, t), t);
                }

                // window-2 row accumulation (fp16 window <= 2 samples)
                if ((k & 1) == 0) {
                    h0 = r0; h1 = r1;
                } else {
                    h0 = __hadd2(h0, r0);
                    h1 = __hadd2(h1, r1);
                    accA0 += __low2float(h0);  accB0 += __high2float(h0);
                    accA1 += __low2float(h1);  accB1 += __high2float(h1);
                }

                // pv in half2: (imageA, imageB) together
                const __half2 pvh = __hadd2(r0, r1);
                const int km = k & 3;
                if (km == 0)      q0 = pvh;
                else if (km == 1) q1 = pvh;
                else if (km == 2) q2 = pvh;
                else {
                    const int kb = k >> 2;
                    // ONE chunk-4 butterfly tree in half2 for BOTH images
                    __half2 x0 = (lane & 16) ? q0 : q2;
                    x0 = shfl_xor_h2(x0, 16);
                    const __half2 f0 = __hadd2((lane & 16) ? q2 : q0, x0);
                    __half2 x1 = (lane & 16) ? q1 : pvh;
                    x1 = shfl_xor_h2(x1, 16);
                    const __half2 f1 = __hadd2((lane & 16) ? pvh : q1, x1);
                    __half2 y = (lane & 8) ? f0 : f1;
                    y = shfl_xor_h2(y, 8);
                    __half2 r = __hadd2((lane & 8) ? f1 : f0, y);
                    r = __hadd2(r, shfl_xor_h2(r, 4));
                    r = __hadd2(r, shfl_xor_h2(r, 2));
                    r = __hadd2(r, shfl_xor_h2(r, 1));
                    if ((lane & 7) == vti + 4 * kb) {
                        vregA += __low2float(r);
                        vregB += __high2float(r);
                    }
                }

                bx = fmaf(8.0f, B, bx);
                by = fmaf(8.0f, Asg, by);
            }
            __syncthreads();   // gather reads done before next tile's copies
        }

        // --- per-u reduction, both images (scratch aliases tile) ---
        float* scratch = (float*)tilew;
        scratch[lane * 8 + wid]              = accA0;
        scratch[(32 + lane) * 8 + wid]       = accA1;
        scratch[512 + lane * 8 + wid]        = accB0;
        scratch[512 + (32 + lane) * 8 + wid] = accB1;
        __syncthreads();
        if (tid < 128) {
            const int img = tid >> 6;       // 0 = A, 1 = B
            const int ul  = tid & 63;
            const float* p = scratch + img * 512 + ul * 8;
            const float tot = ((p[0] + p[1]) + (p[2] + p[3])) +
                              ((p[4] + p[5]) + (p[6] + p[7]));
            const int uu  = u0 + ul;
            const int row = T ? (Hh - 1 - uu) : uu;
            const int ang = T ? (a + 90) : a;
            const int n   = 2 * np + img;
            atomicAdd(&out[((size_t)(n * Ww + row)) * NA + ang], tot);
        }
        // order generic scratch writes before the async-proxy tile writes
        asm volatile("fence.proxy.async.shared::cta;" ::: "memory");
        __syncthreads();
    }

    // --- v-sum epilogue: lane l owns (vti=(l&7)&3, k=4*((l&7)>>2)+(l>>3));
    //     v = v_base + 64*vti + wid + 8*k; 2 contributors per bin. ---
    {
        const int g  = lane >> 3;
        const int w  = lane & 7;
        const int v  = v_base + 64 * (w & 3) + wid + 8 * (4 * (w >> 2) + g);
        const int ang = T ? a : (a + 90);
        const int row = T ? v : (Hh - 1 - v);
        const size_t o = ((size_t)row) * NA + ang;
        atomicAdd(&out[((size_t)(2 * np) * Ww) * NA + o], vregA);
        atomicAdd(&out[((size_t)(2 * np + 1) * Ww) * NA + o], vregB);
    }
}

extern "C" void kernel_launch(void* const* d_in, const int* in_sizes, int n_in,
                              void* d_out, int out_size) {
    (void)in_sizes; (void)n_in;
    const float* x = (const float*)d_in[0];
    float* out = (float*)d_out;

    cudaFuncSetAttribute(radon_kernel,
                         cudaFuncAttributeMaxDynamicSharedMemorySize,
                         SMEM_BYTES);

    cudaMemsetAsync(out, 0, (size_t)out_size * sizeof(float), 0);

    dim3 pgrid((PWORDS + 255) / 256, 16);
    prep_pairs<<<pgrid, 256>>>(x);

    dim3 grid(90, 16, 4);   // (angle pair, image pair, u-half x v-half)
    radon_kernel<<<grid, THREADS, SMEM_BYTES>>>(out);
}

// round 17
// speedup vs baseline: 3.1787x; 1.0156x over previous
#include <cuda_runtime.h>
#include <cuda_fp16.h>
#include <cstdint>

// Radon transform, ray-driven bilinear, matching the JAX reference
// (zero-padded sampling == reference's per-corner valid masking).
//
// x: (32, 1, 512, 512) f32   ->  out: (32, 1, 512, 180) f32
//
// Base (R13-R16): batch-paired half2 words (2 images per word) in a padded
// 704x704 image (16 pairs, 31.7MB, L2-resident); TMA bulk staging
// (cp.async.bulk + mbarrier expect_tx); PITCH=96 + reflection transpose ->
// conflict-free gather; 90-deg symmetry (a and a+90 from one pass);
// half2 butterfly v-reduce + register-resident v-sums; window-2 fp16 row
// accumulation; 2 atomicAdd contributors per output bin (deterministic).
//
// R17 changes (ALU 58% unexplained by static count -> spin-wait suspect):
//  - mbarrier try_wait with SUSPEND HINT (0x989680): waiting warps HW-sleep
//    instead of burning issue slots in an ISETP+BRA poll loop.
//  - shared fx/fy cvt: one cvt.rn.f16x2.f32 packs both u-samples' weight,
//    broadcasts fold into HFMA2 .H0_H0/.H1_H1 operand selectors (4->2 cvt/k).
//  - removed redundant post-reduction __syncthreads (pre-copy barrier
//    already orders scratch reads vs TMA tile writes).

namespace {
constexpr int Hh = 512;
constexpr int Ww = 512;
constexpr int NA = 180;
constexpr int PAD = 96;
constexpr int PDIM = 704;                 // 512 + 2*96
constexpr int PWORDS = PDIM * PDIM;       // per-pair words
constexpr int PITCH = 96;                 // tile words per row (0 mod 32)
constexpr int MAXROWS = 94;               // rows per tile <= 94
constexpr int TILE_WORDS = MAXROWS * PITCH;           // 9024
constexpr int THREADS = 256;                          // 8 warps
constexpr int SMEM_BYTES = TILE_WORDS * 4 + 16;       // tile + mbarrier
constexpr int VS = 256;                               // v-half extent
}

__device__ __align__(16) unsigned g_pairs[16ull * PWORDS];  // 31.7 MB

__device__ __forceinline__ unsigned pack_h2(float a_hi, float b_lo) {
    unsigned d;
    asm("cvt.rn.f16x2.f32 %0, %1, %2;" : "=r"(d) : "f"(a_hi), "f"(b_lo));
    return d;
}

__device__ __forceinline__ __half2 shfl_xor_h2(__half2 v, int m) {
    union { __half2 h; unsigned u; } a;
    a.h = v;
    a.u = __shfl_xor_sync(0xffffffffu, a.u, m);
    return a.h;
}

__device__ __forceinline__ void mbar_init(uint32_t mbar, uint32_t cnt) {
    asm volatile("mbarrier.init.shared.b64 [%0], %1;"
                 :: "r"(mbar), "r"(cnt) : "memory");
}
__device__ __forceinline__ void mbar_expect_tx(uint32_t mbar, uint32_t tx) {
    asm volatile("mbarrier.arrive.expect_tx.shared.b64 _, [%0], %1;"
                 :: "r"(mbar), "r"(tx) : "memory");
}
__device__ __forceinline__ void bulk_copy(uint32_t dst, const void* src,
                                          uint32_t bytes, uint32_t mbar) {
    asm volatile("cp.async.bulk.shared::cta.global"
                 ".mbarrier::complete_tx::bytes [%0], [%1], %2, [%3];"
                 :: "r"(dst), "l"(src), "r"(bytes), "r"(mbar) : "memory");
}
// try_wait with suspend hint: waiting warps HW-sleep, don't spin issue slots
__device__ __forceinline__ void mbar_wait(uint32_t mbar, uint32_t parity) {
    asm volatile(
        "{\n\t"
        ".reg .pred P;\n"
        "W_%=:\n\t"
        "mbarrier.try_wait.parity.acquire.cta.shared::cta.b64 P, [%0], %1, 0x989680;\n\t"
        "@!P bra W_%=;\n\t"
        "}"
        :: "r"(mbar), "r"(parity) : "memory");
}

__global__ __launch_bounds__(256, 8)
void prep_pairs(const float* __restrict__ x) {
    const int np = blockIdx.y;            // 0..15
    const int idx = blockIdx.x * 256 + threadIdx.x;
    if (idx >= PWORDS) return;
    const int prow = idx / PDIM;
    const int pcol = idx - prow * PDIM;
    const int r = prow - PAD;
    const int cc = pcol - PAD;
    float va = 0.f, vb = 0.f;
    if (((unsigned)r < (unsigned)Hh) & ((unsigned)cc < (unsigned)Ww)) {
        va = x[((size_t)(2 * np) * Hh + r) * Ww + cc];
        vb = x[((size_t)(2 * np + 1) * Hh + r) * Ww + cc];
    }
    g_pairs[(size_t)np * PWORDS + idx] = pack_h2(vb, va);
}

__global__ __launch_bounds__(THREADS, 6)
void radon_kernel(float* __restrict__ out) {
    extern __shared__ float sm[];
    unsigned* tilew = (unsigned*)sm;        // 9024 words (aliased scratch)
    const uint32_t smem_u32 = (uint32_t)__cvta_generic_to_shared(sm);
    const uint32_t mbar = smem_u32 + TILE_WORDS * 4;

    const int tid  = threadIdx.x;
    const int lane = tid & 31;
    const int wid  = tid >> 5;
    const int a    = blockIdx.x;   // 0..89
    const int np   = blockIdx.y;   // 0..15 (image pair)
    const int zu   = blockIdx.z & 1;
    const int zv   = blockIdx.z >> 1;
    const int v_base = zv * VS;

    const float theta = (float)a * 0.017453292519943295f;
    float s0, c0;
    sincosf(theta, &s0, &c0);

    // reflection transpose: keep ix lane-stride = max(c0,s0) >= 0.71
    const bool T = (s0 > c0);
    const float A = T ? s0 : c0;            // d(ix)/dfu
    const float B = T ? c0 : s0;            // d(ix)/dfv
    const float Asg = T ? -A : A;           // sg*A
    const float Bsg = T ? -B : B;           // sg*B

    const unsigned* __restrict__ gp = g_pairs + (size_t)np * PWORDS;

    if (tid == 0) mbar_init(mbar, 1);
    __syncthreads();

    float vregA = 0.f, vregB = 0.f;         // per-lane v-sum slots
    int ph = 0;                             // staged-tile parity

    for (int ut = 0; ut < 4; ++ut) {
        const int u0 = (zu * 4 + ut) * 64;
        const float fu_lo = (float)u0 - 255.5f;
        const float fu_hi = fu_lo + 63.0f;
        float accA0 = 0.f, accA1 = 0.f, accB0 = 0.f, accB1 = 0.f;

        for (int vti = 0; vti < 4; ++vti) {
            const int vt = v_base + vti * 64;
            const float fv_lo = (float)vt - 255.5f;
            const float fv_hi = fv_lo + 63.0f;

            // ix monotone (A,B >= 0)
            const float ixmin = fmaf(A, fu_lo, fmaf(B, fv_lo, 255.5f));
            const float ixmax = fmaf(A, fu_hi, fmaf(B, fv_hi, 255.5f));
            // iy corners
            const float y00 = fmaf(-Bsg, fu_lo, Asg * fv_lo);
            const float y01 = fmaf(-Bsg, fu_lo, Asg * fv_hi);
            const float y10 = fmaf(-Bsg, fu_hi, Asg * fv_lo);
            const float y11 = fmaf(-Bsg, fu_hi, Asg * fv_hi);
            const float iymin = 255.5f + fminf(fminf(y00, y01), fminf(y10, y11));
            const float iymax = 255.5f + fmaxf(fmaxf(y00, y01), fmaxf(y10, y11));

            const int c_lo = (int)floorf(ixmin) - 1;
            const int cols = (int)floorf(ixmax) - c_lo + 2;   // <= 93
            const int r_lo = (int)floorf(iymin) - 1;
            const int rows = (int)floorf(iymax) - r_lo + 3;   // <= 94

            // tile entirely outside the image -> contribution exactly 0
            if ((c_lo >= Ww) | (r_lo >= Hh) |
                (c_lo + cols <= 0) | (r_lo + rows <= 0))
                continue;

            const int cs = c_lo & ~3;       // 16B-aligned staging origin
            const int nb16 = (((c_lo + cols - cs) * 4) + 15) & ~15;  // <=384

            // --- TMA bulk staging: one bulk copy per tile row ---
            if (tid == 0) mbar_expect_tx(mbar, (uint32_t)(rows * nb16));
            __syncthreads();                 // expect_tx before any copy;
                                             // also orders prior scratch
                                             // reads vs these tile writes
            if (lane == 0) {
                const char* src = (const char*)
                    (gp + (size_t)(r_lo + PAD + wid) * PDIM + (cs + PAD));
                uint32_t dst = smem_u32 + (uint32_t)(wid * PITCH * 4);
                for (int r = wid; r < rows; r += 8) {
                    bulk_copy(dst, src, (uint32_t)nb16, mbar);
                    src += 8 * PDIM * 4;
                    dst += 8 * PITCH * 4;
                }
            }
            mbar_wait(mbar, (uint32_t)(ph & 1));
            ++ph;

            // --- gather: full half2 bilinear, BOTH images per LDS set ---
            const __half2* tp = (const __half2*)tilew;
            const float fu = (float)(u0 + lane) - 255.5f;
            const float fv = (float)(vt + wid) - 255.5f;
            float bx = fmaf(A, fu, fmaf(B, fv, 255.5f)) - (float)cs;
            float by = fmaf(-Bsg, fu, fmaf(Asg, fv,
                            255.5f - (float)r_lo));

            __half2 h0, h1;                 // window-2 row accumulators
            __half2 q0, q1, q2;             // pv chunk storage (both images)
            #pragma unroll
            for (int k = 0; k < 8; ++k) {
                // coordinates + floors for both u-samples
                const float ix1 = fmaf(32.0f, A, bx);
                const float iy1 = fmaf(-32.0f, Bsg, by);
                const float fx00 = floorf(bx),  fy00 = floorf(by);
                const float fx01 = floorf(ix1), fy01 = floorf(iy1);
                const int idx0 = (int)fmaf(fy00, (float)PITCH, fx00);
                const int idx1 = (int)fmaf(fy01, (float)PITCH, fx01);
                // shared cvt: one f16x2 pack per weight axis
                union { unsigned u; __half2 h; } hx, hy;
                hx.u = pack_h2(ix1 - fx01, bx - fx00);  // (lo=fx_s0, hi=fx_s1)
                hy.u = pack_h2(iy1 - fy01, by - fy00);

                __half2 r0, r1;
                {   // u = u0 + lane
                    const __half2 w00 = tp[idx0];
                    const __half2 w01 = tp[idx0 + 1];
                    const __half2 w10 = tp[idx0 + PITCH];
                    const __half2 w11 = tp[idx0 + PITCH + 1];
                    const __half2 fx2 = __low2half2(hx.h);
                    const __half2 fy2 = __low2half2(hy.h);
                    const __half2 t = __hfma2(fx2, __hsub2(w01, w00), w00);
                    const __half2 b = __hfma2(fx2, __hsub2(w11, w10), w10);
                    r0 = __hfma2(fy2, __hsub2(b, t), t);
                }
                {   // u = u0 + 32 + lane
                    const __half2 w00 = tp[idx1];
                    const __half2 w01 = tp[idx1 + 1];
                    const __half2 w10 = tp[idx1 + PITCH];
                    const __half2 w11 = tp[idx1 + PITCH + 1];
                    const __half2 fx2 = __high2half2(hx.h);
                    const __half2 fy2 = __high2half2(hy.h);
                    const __half2 t = __hfma2(fx2, __hsub2(w01, w00), w00);
                    const __half2 b = __hfma2(fx2, __hsub2(w11, w10), w10);
                    r1 = __hfma2(fy2, __hsub2(b, t), t);
                }

                // window-2 row accumulation (fp16 window <= 2 samples)
                if ((k & 1) == 0) {
                    h0 = r0; h1 = r1;
                } else {
                    h0 = __hadd2(h0, r0);
                    h1 = __hadd2(h1, r1);
                    accA0 += __low2float(h0);  accB0 += __high2float(h0);
                    accA1 += __low2float(h1);  accB1 += __high2float(h1);
                }

                // pv in half2: (imageA, imageB) together
                const __half2 pvh = __hadd2(r0, r1);
                const int km = k & 3;
                if (km == 0)      q0 = pvh;
                else if (km == 1) q1 = pvh;
                else if (km == 2) q2 = pvh;
                else {
                    const int kb = k >> 2;
                    // ONE chunk-4 butterfly tree in half2 for BOTH images
                    __half2 x0 = (lane & 16) ? q0 : q2;
                    x0 = shfl_xor_h2(x0, 16);
                    const __half2 f0 = __hadd2((lane & 16) ? q2 : q0, x0);
                    __half2 x1 = (lane & 16) ? q1 : pvh;
                    x1 = shfl_xor_h2(x1, 16);
                    const __half2 f1 = __hadd2((lane & 16) ? pvh : q1, x1);
                    __half2 y = (lane & 8) ? f0 : f1;
                    y = shfl_xor_h2(y, 8);
                    __half2 r = __hadd2((lane & 8) ? f1 : f0, y);
                    r = __hadd2(r, shfl_xor_h2(r, 4));
                    r = __hadd2(r, shfl_xor_h2(r, 2));
                    r = __hadd2(r, shfl_xor_h2(r, 1));
                    if ((lane & 7) == vti + 4 * kb) {
                        vregA += __low2float(r);
                        vregB += __high2float(r);
                    }
                }

                bx = fmaf(8.0f, B, bx);
                by = fmaf(8.0f, Asg, by);
            }
            __syncthreads();   // gather reads done before next tile's copies
        }

        // --- per-u reduction, both images (scratch aliases tile) ---
        float* scratch = (float*)tilew;
        scratch[lane * 8 + wid]              = accA0;
        scratch[(32 + lane) * 8 + wid]       = accA1;
        scratch[512 + lane * 8 + wid]        = accB0;
        scratch[512 + (32 + lane) * 8 + wid] = accB1;
        __syncthreads();
        if (tid < 128) {
            const int img = tid >> 6;       // 0 = A, 1 = B
            const int ul  = tid & 63;
            const float* p = scratch + img * 512 + ul * 8;
            const float tot = ((p[0] + p[1]) + (p[2] + p[3])) +
                              ((p[4] + p[5]) + (p[6] + p[7]));
            const int uu  = u0 + ul;
            const int row = T ? (Hh - 1 - uu) : uu;
            const int ang = T ? (a + 90) : a;
            const int n   = 2 * np + img;
            atomicAdd(&out[((size_t)(n * Ww + row)) * NA + ang], tot);
        }
        // generic scratch accesses ordered before the async-proxy tile
        // writes; the next tile's pre-copy __syncthreads sequences threads
        asm volatile("fence.proxy.async.shared::cta;" ::: "memory");
    }

    // --- v-sum epilogue: lane l owns (vti=(l&7)&3, k=4*((l&7)>>2)+(l>>3));
    //     v = v_base + 64*vti + wid + 8*k; 2 contributors per bin. ---
    {
        const int g  = lane >> 3;
        const int w  = lane & 7;
        const int v  = v_base + 64 * (w & 3) + wid + 8 * (4 * (w >> 2) + g);
        const int ang = T ? a : (a + 90);
        const int row = T ? v : (Hh - 1 - v);
        const size_t o = ((size_t)row) * NA + ang;
        atomicAdd(&out[((size_t)(2 * np) * Ww) * NA + o], vregA);
        atomicAdd(&out[((size_t)(2 * np + 1) * Ww) * NA + o], vregB);
    }
}

extern "C" void kernel_launch(void* const* d_in, const int* in_sizes, int n_in,
                              void* d_out, int out_size) {
    (void)in_sizes; (void)n_in;
    const float* x = (const float*)d_in[0];
    float* out = (float*)d_out;

    cudaFuncSetAttribute(radon_kernel,
                         cudaFuncAttributeMaxDynamicSharedMemorySize,
                         SMEM_BYTES);

    cudaMemsetAsync(out, 0, (size_t)out_size * sizeof(float), 0);

    dim3 pgrid((PWORDS + 255) / 256, 16);
    prep_pairs<<<pgrid, 256>>>(x);

    dim3 grid(90, 16, 4);   // (angle pair, image pair, u-half x v-half)
    radon_kernel<<<grid, THREADS, SMEM_BYTES>>>(out);
}